// round 13
// baseline (speedup 1.0000x reference)
#include <cuda_runtime.h>
#include <cuda_bf16.h>
#include <cstdint>

#define BT 4096
#define T_ 1024
#define E_ 512
#define H_ 8
#define L_ 8
#define V_ 128
#define EPS_ 0.1f
#define KB3 1536

// ---------------- scratch (device globals) ----------------------------------
__device__ float g_x[BT * E_];
__device__ float g_qkv[BT * 3 * E_];   // logits fallback scratch only
__device__ float g_h[BT * E_];         // (unused fp32 hidden, kept)
__device__ float g_b2[BT * E_];
__device__ float g_o1[BT * E_];
__device__ int   g_is64[2];

__device__ __nv_bfloat16 g_ab1[BT * KB3];
__device__ __nv_bfloat16 g_ab2[BT * KB3];
__device__ __nv_bfloat16 g_wqkv[L_ * 1536 * KB3];
__device__ __nv_bfloat16 g_w1[L_ * 512 * KB3];
__device__ __nv_bfloat16 g_w2[L_ * 512 * KB3];
__device__ __nv_bfloat16 g_w3[L_ * 512 * KB3];
__device__ __nv_bfloat16 g_w4[L_ * 512 * KB3];

__device__ __nv_bfloat16 g_qh[32 * 1024 * 64];
__device__ __nv_bfloat16 g_ql[32 * 1024 * 64];
__device__ __nv_bfloat16 g_kh[32 * 1024 * 64];
__device__ __nv_bfloat16 g_kl[32 * 1024 * 64];
__device__ __nv_bfloat16 g_vh[32 * 1024 * 64];
__device__ __nv_bfloat16 g_vl[32 * 1024 * 64];
__device__ float g_vsuf[32 * 17 * 64];

// ---------------- PTX helpers ------------------------------------------------
#define SW128(o) ((o) ^ (((o) >> 3) & 0x70))
#define CP_ASYNC16(dst, src) \
    asm volatile("cp.async.cg.shared.global [%0], [%1], 16;" :: "r"(dst), "l"(src))
#define CP_COMMIT() asm volatile("cp.async.commit_group;" ::: "memory")
#define CP_WAIT1() asm volatile("cp.async.wait_group 1;" ::: "memory")
#define CP_WAIT0() asm volatile("cp.async.wait_group 0;" ::: "memory")

#define LDMATRIX_X4(r0, r1, r2, r3, addr)                                      \
    asm volatile("ldmatrix.sync.aligned.m8n8.x4.shared.b16 {%0,%1,%2,%3}, [%4];" \
                 : "=r"(r0), "=r"(r1), "=r"(r2), "=r"(r3) : "r"(addr))

#define LDMATRIX_X4T(r0, r1, r2, r3, addr)                                     \
    asm volatile("ldmatrix.sync.aligned.m8n8.x4.trans.shared.b16 {%0,%1,%2,%3}, [%4];" \
                 : "=r"(r0), "=r"(r1), "=r"(r2), "=r"(r3) : "r"(addr))

#define MMA16816(d, a, b0, b1)                                                 \
    asm volatile("mma.sync.aligned.m16n8k16.row.col.f32.bf16.bf16.f32 "        \
                 "{%0,%1,%2,%3}, {%4,%5,%6,%7}, {%8,%9}, {%0,%1,%2,%3};"       \
                 : "+f"((d)[0]), "+f"((d)[1]), "+f"((d)[2]), "+f"((d)[3])      \
                 : "r"((a)[0]), "r"((a)[1]), "r"((a)[2]), "r"((a)[3]),         \
                   "r"(b0), "r"(b1))

__device__ __forceinline__ uint32_t pack_hi_res(float a, float b, float& ra, float& rb) {
    __nv_bfloat16 h0 = __float2bfloat16(a), h1 = __float2bfloat16(b);
    ra = a - __bfloat162float(h0);
    rb = b - __bfloat162float(h1);
    return ((uint32_t)__bfloat16_as_ushort(h1) << 16) | (uint32_t)__bfloat16_as_ushort(h0);
}
__device__ __forceinline__ uint32_t pack2bf(float a, float b) {
    __nv_bfloat162 t = __floats2bfloat162_rn(a, b);
    return *reinterpret_cast<uint32_t*>(&t);
}
// activation split store: [hi | lo | hi] at cols c, c+512, c+1024
__device__ __forceinline__ void store_split2(__nv_bfloat16* ab, size_t base,
                                             float a, float b) {
    __nv_bfloat16 h0 = __float2bfloat16(a), h1 = __float2bfloat16(b);
    __nv_bfloat162 hh, ll;
    hh.x = h0; hh.y = h1;
    ll.x = __float2bfloat16(a - __bfloat162float(h0));
    ll.y = __float2bfloat16(b - __bfloat162float(h1));
    *(__nv_bfloat162*)&ab[base] = hh;
    *(__nv_bfloat162*)&ab[base + 512] = ll;
    *(__nv_bfloat162*)&ab[base + 1024] = hh;
}
__device__ __forceinline__ void store_plane2(__nv_bfloat16* hp, __nv_bfloat16* lp,
                                             size_t dst, float a, float b) {
    __nv_bfloat16 h0 = __float2bfloat16(a), h1 = __float2bfloat16(b);
    __nv_bfloat162 hh, ll;
    hh.x = h0; hh.y = h1;
    ll.x = __float2bfloat16(a - __bfloat162float(h0));
    ll.y = __float2bfloat16(b - __bfloat162float(h1));
    *(__nv_bfloat162*)&hp[dst] = hh;
    *(__nv_bfloat162*)&lp[dst] = ll;
}

// ---------------- weight split conversion: [hi|hi|lo] -----------------------
__global__ __launch_bounds__(128) void conv_split_w(
    const float* __restrict__ X, __nv_bfloat16* __restrict__ O) {
    size_t r = blockIdx.x;
    int c = threadIdx.x * 4;
    float4 v = *(const float4*)&X[r * 512 + c];
    float f[4] = {v.x, v.y, v.z, v.w};
    __nv_bfloat16 h[4], lo[4];
#pragma unroll
    for (int i = 0; i < 4; i++) {
        h[i] = __float2bfloat16(f[i]);
        lo[i] = __float2bfloat16(f[i] - __bfloat162float(h[i]));
    }
    __nv_bfloat16* o = O + r * KB3 + c;
    __nv_bfloat162 h01, h23, l01, l23;
    h01.x = h[0]; h01.y = h[1]; h23.x = h[2]; h23.y = h[3];
    l01.x = lo[0]; l01.y = lo[1]; l23.x = lo[2]; l23.y = lo[3];
    *(__nv_bfloat162*)&o[0] = h01;
    *(__nv_bfloat162*)&o[2] = h23;
    *(__nv_bfloat162*)&o[512] = h01;
    *(__nv_bfloat162*)&o[514] = h23;
    *(__nv_bfloat162*)&o[1024] = l01;
    *(__nv_bfloat162*)&o[1026] = l23;
}

// ---------------- V suffix sums from planes ----------------------------------
__global__ __launch_bounds__(64) void vsuf_kernel(
    const __nv_bfloat16* __restrict__ vh, const __nv_bfloat16* __restrict__ vl,
    float* __restrict__ vsuf) {
    int bh = blockIdx.x, d = threadIdx.x;
    float s = 0.f;
    vsuf[((size_t)bh * 17 + 16) * 64 + d] = 0.f;
    for (int jt = 15; jt >= 0; jt--) {
        const __nv_bfloat16* ph = vh + ((size_t)bh * 1024 + jt * 64) * 64 + d;
        const __nv_bfloat16* pl = vl + ((size_t)bh * 1024 + jt * 64) * 64 + d;
#pragma unroll 4
        for (int t = 0; t < 64; t++)
            s += __bfloat162float(ph[(size_t)t * 64]) + __bfloat162float(pl[(size_t)t * 64]);
        vsuf[((size_t)bh * 17 + jt) * 64 + d] = s;
    }
}

// ---------------- tensor-core flash attention --------------------------------
#define ATT_SMEM 81920
#define AQH 0
#define AQL 8192
#define AST(s) (16384 + (s) * 32768)

__device__ __forceinline__ void att_load_kv(
    uint32_t sb, int stage, size_t base,
    const __nv_bfloat16* kh, const __nv_bfloat16* kl,
    const __nv_bfloat16* vh, const __nv_bfloat16* vl, int kt, int tid) {
    uint32_t st = sb + AST(stage);
#pragma unroll
    for (int i = 0; i < 4; i++) {
        int g = i * 128 + tid, r = g >> 3, seg = g & 7;
        uint32_t off = SW128(r * 128 + seg * 16);
        size_t so = (base + (size_t)(kt * 64 + r) * 64) * 2 + seg * 16;
        CP_ASYNC16(st + off,         (const char*)kh + so);
        CP_ASYNC16(st + 8192 + off,  (const char*)kl + so);
        CP_ASYNC16(st + 16384 + off, (const char*)vh + so);
        CP_ASYNC16(st + 24576 + off, (const char*)vl + so);
    }
    CP_COMMIT();
}

__global__ __launch_bounds__(128) void attn_mma(
    const __nv_bfloat16* __restrict__ qh, const __nv_bfloat16* __restrict__ ql,
    const __nv_bfloat16* __restrict__ kh, const __nv_bfloat16* __restrict__ kl,
    const __nv_bfloat16* __restrict__ vh, const __nv_bfloat16* __restrict__ vl,
    const float* __restrict__ vsuf, __nv_bfloat16* __restrict__ AB) {
    extern __shared__ char sm[];
    uint32_t sb = (uint32_t)__cvta_generic_to_shared(sm);
    int tid = threadIdx.x, wid = tid >> 5, lane = tid & 31;
    int qt = blockIdx.x, bh = blockIdx.y;
    int b = bh >> 3, h = bh & 7;
    size_t base = (size_t)bh * 1024 * 64;
    int q0 = qt * 64;
    int g = lane >> 2, qd = lane & 3;

#pragma unroll
    for (int i = 0; i < 4; i++) {
        int gg = i * 128 + tid, r = gg >> 3, seg = gg & 7;
        uint32_t off = SW128(r * 128 + seg * 16);
        size_t so = (base + (size_t)(q0 + r) * 64) * 2 + seg * 16;
        CP_ASYNC16(sb + AQH + off, (const char*)qh + so);
        CP_ASYNC16(sb + AQL + off, (const char*)ql + so);
    }
    CP_COMMIT();
    att_load_kv(sb, 0, base, kh, kl, vh, vl, 0, tid);

    float Oa[8][4];
#pragma unroll
    for (int j = 0; j < 8; j++)
#pragma unroll
        for (int e = 0; e < 4; e++) Oa[j][e] = 0.f;
    float mrow0 = 0.f, mrow1 = 0.f, lrow0 = 0.f, lrow1 = 0.f;

    int qA = q0 + wid * 16 + g, qB = qA + 8;
    uint32_t arow = (uint32_t)(wid * 16 + (lane & 15));
    uint32_t acb = (uint32_t)((lane >> 4) << 4);
    int bq = lane >> 3, br = lane & 7;
    uint32_t brbase = (uint32_t)(((bq >> 1) << 3) + br);
    uint32_t bcb = (uint32_t)((bq & 1) << 4);
    uint32_t vrow = (uint32_t)(((lane >> 3) & 1) * 8 + (lane & 7));
    uint32_t vcb = (uint32_t)((lane >> 4) << 4);

    for (int kt = 0; kt <= qt; kt++) {
        if (kt < qt) att_load_kv(sb, (kt + 1) & 1, base, kh, kl, vh, vl, kt + 1, tid);
        if (kt < qt) { CP_WAIT1(); } else { CP_WAIT0(); }
        __syncthreads();
        uint32_t st = sb + AST(kt & 1);

        float Sf[8][4];
#pragma unroll
        for (int j = 0; j < 8; j++)
#pragma unroll
            for (int e = 0; e < 4; e++) Sf[j][e] = 0.f;
#pragma unroll
        for (int ks = 0; ks < 12; ks++) {
            int grp = ks >> 2, kk2 = ks & 3;
            uint32_t qpl = sb + (grp == 1 ? AQL : AQH);
            uint32_t kpl = st + (grp == 2 ? 8192u : 0u);
            uint32_t af[4];
            LDMATRIX_X4(af[0], af[1], af[2], af[3],
                        qpl + SW128(arow * 128 + kk2 * 32 + acb));
#pragma unroll
            for (int np = 0; np < 4; np++) {
                uint32_t bf[4];
                uint32_t boff = SW128((np * 16 + brbase) * 128 + kk2 * 32 + bcb);
                LDMATRIX_X4(bf[0], bf[1], bf[2], bf[3], kpl + boff);
                MMA16816(Sf[2 * np], af, bf[0], bf[1]);
                MMA16816(Sf[2 * np + 1], af, bf[2], bf[3]);
            }
        }

        bool diag = (kt == qt);
        float tm0 = -1e30f, tm1 = -1e30f;
#pragma unroll
        for (int j = 0; j < 8; j++) {
            int k0 = kt * 64 + j * 8 + qd * 2;
            float s0 = Sf[j][0] * 0.125f, s1 = Sf[j][1] * 0.125f;
            float s2 = Sf[j][2] * 0.125f, s3 = Sf[j][3] * 0.125f;
            if (diag) {
                if (k0 > qA) s0 = 0.f;
                if (k0 + 1 > qA) s1 = 0.f;
                if (k0 > qB) s2 = 0.f;
                if (k0 + 1 > qB) s3 = 0.f;
            }
            Sf[j][0] = s0; Sf[j][1] = s1; Sf[j][2] = s2; Sf[j][3] = s3;
            tm0 = fmaxf(tm0, fmaxf(s0, s1));
            tm1 = fmaxf(tm1, fmaxf(s2, s3));
        }
        tm0 = fmaxf(tm0, __shfl_xor_sync(0xffffffffu, tm0, 1));
        tm0 = fmaxf(tm0, __shfl_xor_sync(0xffffffffu, tm0, 2));
        tm1 = fmaxf(tm1, __shfl_xor_sync(0xffffffffu, tm1, 1));
        tm1 = fmaxf(tm1, __shfl_xor_sync(0xffffffffu, tm1, 2));
        float mn0 = fmaxf(mrow0, tm0), mn1 = fmaxf(mrow1, tm1);
        float al0 = __expf(mrow0 - mn0), al1 = __expf(mrow1 - mn1);
        mrow0 = mn0; mrow1 = mn1;
        float ps0 = 0.f, ps1 = 0.f;
#pragma unroll
        for (int j = 0; j < 8; j++) {
            float p0 = __expf(Sf[j][0] - mn0), p1 = __expf(Sf[j][1] - mn0);
            float p2 = __expf(Sf[j][2] - mn1), p3 = __expf(Sf[j][3] - mn1);
            Sf[j][0] = p0; Sf[j][1] = p1; Sf[j][2] = p2; Sf[j][3] = p3;
            ps0 += p0 + p1; ps1 += p2 + p3;
            Oa[j][0] *= al0; Oa[j][1] *= al0; Oa[j][2] *= al1; Oa[j][3] *= al1;
        }
        ps0 += __shfl_xor_sync(0xffffffffu, ps0, 1);
        ps0 += __shfl_xor_sync(0xffffffffu, ps0, 2);
        ps1 += __shfl_xor_sync(0xffffffffu, ps1, 1);
        ps1 += __shfl_xor_sync(0xffffffffu, ps1, 2);
        lrow0 = lrow0 * al0 + ps0;
        lrow1 = lrow1 * al1 + ps1;

#pragma unroll
        for (int kk = 0; kk < 4; kk++) {
            int j0 = 2 * kk, j1 = 2 * kk + 1;
            float r0, r1;
            uint32_t ah[4], alr[4];
            ah[0] = pack_hi_res(Sf[j0][0], Sf[j0][1], r0, r1); alr[0] = pack2bf(r0, r1);
            ah[1] = pack_hi_res(Sf[j0][2], Sf[j0][3], r0, r1); alr[1] = pack2bf(r0, r1);
            ah[2] = pack_hi_res(Sf[j1][0], Sf[j1][1], r0, r1); alr[2] = pack2bf(r0, r1);
            ah[3] = pack_hi_res(Sf[j1][2], Sf[j1][3], r0, r1); alr[3] = pack2bf(r0, r1);
#pragma unroll
            for (int dg = 0; dg < 4; dg++) {
                uint32_t voff = SW128((kk * 16 + vrow) * 128 + dg * 32 + vcb);
                uint32_t vh0, vh1, vh2, vh3, vl0, vl1, vl2, vl3;
                LDMATRIX_X4T(vh0, vh1, vh2, vh3, st + 16384 + voff);
                LDMATRIX_X4T(vl0, vl1, vl2, vl3, st + 24576 + voff);
                MMA16816(Oa[2 * dg], ah, vh0, vh1);
                MMA16816(Oa[2 * dg], alr, vh0, vh1);
                MMA16816(Oa[2 * dg], ah, vl0, vl1);
                MMA16816(Oa[2 * dg + 1], ah, vh2, vh3);
                MMA16816(Oa[2 * dg + 1], alr, vh2, vh3);
                MMA16816(Oa[2 * dg + 1], ah, vl2, vl3);
            }
        }
        __syncthreads();
    }

    float wf0 = __expf(-mrow0), wf1 = __expf(-mrow1);
    float nfut = (float)(1024 - (qt + 1) * 64);
    float inv0 = 1.f / (lrow0 + wf0 * nfut);
    float inv1 = 1.f / (lrow1 + wf1 * nfut);
    const float* vs = vsuf + ((size_t)bh * 17 + qt + 1) * 64;
    size_t rowA = (size_t)b * 1024 + qA;
    size_t rowB = rowA + 8;
#pragma unroll
    for (int j = 0; j < 8; j++) {
        int d = j * 8 + qd * 2;
        float v0 = vs[d], v1 = vs[d + 1];
        int col = h * 64 + d;
        store_split2(AB, rowA * KB3 + col,
                     (Oa[j][0] + wf0 * v0) * inv0, (Oa[j][1] + wf0 * v1) * inv0);
        store_split2(AB, rowB * KB3 + col,
                     (Oa[j][2] + wf1 * v0) * inv1, (Oa[j][3] + wf1 * v1) * inv1);
    }
}

// ---------------- mma.sync GEMM with fused epilogues -------------------------
// OUT=0: fp32 C[M,N]+bias(+relu)   OUT=1: split-bf16 activation buffer (N=512)
// OUT=2: qkv -> attention head planes (N=1536)
#define STAGE_BYTES 32768
#define SMEM_MMA (3 * STAGE_BYTES)
#define NCHUNK 24

__device__ __forceinline__ void mma_load_chunk(
    uint32_t sbase, int stage,
    const __nv_bfloat16* A, const __nv_bfloat16* Bw,
    int m0, int n0, int c, int tid) {
    uint32_t abase = sbase + stage * STAGE_BYTES;
    uint32_t bbase = abase + 16384;
#pragma unroll
    for (int i = 0; i < 4; i++) {
        int g = i * 256 + tid, row = g >> 3, seg = g & 7;
        uint32_t dst = abase + SW128(row * 128 + seg * 16);
        const char* src = (const char*)A + (size_t)(m0 + row) * 3072 + c * 128 + seg * 16;
        CP_ASYNC16(dst, src);
    }
#pragma unroll
    for (int i = 0; i < 4; i++) {
        int g = i * 256 + tid, row = g >> 3, seg = g & 7;
        uint32_t dst = bbase + SW128(row * 128 + seg * 16);
        const char* src = (const char*)Bw + (size_t)(n0 + row) * 3072 + c * 128 + seg * 16;
        CP_ASYNC16(dst, src);
    }
    CP_COMMIT();
}

template <int RELU, int OUT>
__global__ __launch_bounds__(256) void gemm_mma(
    const __nv_bfloat16* __restrict__ A, const __nv_bfloat16* __restrict__ Bw,
    const float* __restrict__ bias, float* __restrict__ C,
    __nv_bfloat16* __restrict__ AB,
    __nv_bfloat16* __restrict__ qh, __nv_bfloat16* __restrict__ ql,
    __nv_bfloat16* __restrict__ kh, __nv_bfloat16* __restrict__ kl,
    __nv_bfloat16* __restrict__ vh, __nv_bfloat16* __restrict__ vl,
    int N) {
    extern __shared__ char smem[];
    uint32_t sbase = (uint32_t)__cvta_generic_to_shared(smem);
    int tid = threadIdx.x, wid = tid >> 5, lane = tid & 31;
    int m0 = blockIdx.y * 128, n0 = blockIdx.x * 128;
    int warp_m = wid & 3, warp_n = wid >> 2;

    float acc[2][8][4];
#pragma unroll
    for (int mt = 0; mt < 2; mt++)
#pragma unroll
        for (int nt = 0; nt < 8; nt++)
#pragma unroll
            for (int e = 0; e < 4; e++) acc[mt][nt][e] = 0.f;

    mma_load_chunk(sbase, 0, A, Bw, m0, n0, 0, tid);
    mma_load_chunk(sbase, 1, A, Bw, m0, n0, 1, tid);

    int a_row = warp_m * 32 + (lane & 15);
    int a_col8 = (lane >> 4) << 3;
    int bq = lane >> 3, br = lane & 7;
    int b_n = warp_n * 64 + ((bq >> 1) << 3) + br;
    int b_col8 = (bq & 1) << 3;

    for (int c = 0; c < NCHUNK; c++) {
        if (c + 1 < NCHUNK) { CP_WAIT1(); } else { CP_WAIT0(); }
        __syncthreads();
        if (c + 2 < NCHUNK)
            mma_load_chunk(sbase, (c + 2) % 3, A, Bw, m0, n0, c + 2, tid);

        uint32_t abase = sbase + (c % 3) * STAGE_BYTES;
        uint32_t bbase = abase + 16384;
#pragma unroll
        for (int ks = 0; ks < 4; ks++) {
            uint32_t af[2][4];
#pragma unroll
            for (int mt = 0; mt < 2; mt++) {
                uint32_t off = (uint32_t)((a_row + mt * 16) * 128 + (ks * 16 + a_col8) * 2);
                LDMATRIX_X4(af[mt][0], af[mt][1], af[mt][2], af[mt][3],
                            abase + SW128(off));
            }
#pragma unroll
            for (int np = 0; np < 4; np++) {
                uint32_t bf[4];
                uint32_t off = (uint32_t)((b_n + np * 16) * 128 + (ks * 16 + b_col8) * 2);
                LDMATRIX_X4(bf[0], bf[1], bf[2], bf[3], bbase + SW128(off));
#pragma unroll
                for (int mt = 0; mt < 2; mt++) {
                    MMA16816(acc[mt][2 * np], af[mt], bf[0], bf[1]);
                    MMA16816(acc[mt][2 * np + 1], af[mt], bf[2], bf[3]);
                }
            }
        }
    }

    int g = lane >> 2, q = lane & 3;
#pragma unroll
    for (int mt = 0; mt < 2; mt++) {
        int row0 = m0 + warp_m * 32 + mt * 16 + g;
#pragma unroll
        for (int nt = 0; nt < 8; nt++) {
            int col = n0 + warp_n * 64 + nt * 8 + q * 2;
            float b0 = bias[col], b1 = bias[col + 1];
            float v0 = acc[mt][nt][0] + b0, v1 = acc[mt][nt][1] + b1;
            float v2 = acc[mt][nt][2] + b0, v3 = acc[mt][nt][3] + b1;
            if (RELU) {
                v0 = fmaxf(v0, 0.f); v1 = fmaxf(v1, 0.f);
                v2 = fmaxf(v2, 0.f); v3 = fmaxf(v3, 0.f);
            }
            if (OUT == 0) {
                *(float2*)&C[(size_t)row0 * N + col] = make_float2(v0, v1);
                *(float2*)&C[(size_t)(row0 + 8) * N + col] = make_float2(v2, v3);
            } else if (OUT == 1) {
                store_split2(AB, (size_t)row0 * KB3 + col, v0, v1);
                store_split2(AB, (size_t)(row0 + 8) * KB3 + col, v2, v3);
            } else {
                int h = col / 192, r = col - h * 192;
                int typ = r >> 6, d = r & 63;
                __nv_bfloat16* hp = (typ == 0) ? qh : (typ == 1) ? kh : vh;
                __nv_bfloat16* lp = (typ == 0) ? ql : (typ == 1) ? kl : vl;
                int b0r = row0 >> 10, t0 = row0 & 1023;
                size_t dst0 = ((size_t)(b0r * 8 + h) * 1024 + t0) * 64 + d;
                int b1r = (row0 + 8) >> 10, t1 = (row0 + 8) & 1023;
                size_t dst1 = ((size_t)(b1r * 8 + h) * 1024 + t1) * 64 + d;
                store_plane2(hp, lp, dst0, v0, v1);
                store_plane2(hp, lp, dst1, v2, v3);
            }
        }
    }
}

// ---------------- int64-vs-int32 detection ----------------------------------
__global__ void detect_kernel(const int* __restrict__ p, int n, int slot) {
    __shared__ int red[256];
    int acc = 0;
    for (int j = 2 * threadIdx.x + 1; j < n; j += 512) acc |= p[j];
    red[threadIdx.x] = acc;
    __syncthreads();
    for (int s = 128; s > 0; s >>= 1) {
        if (threadIdx.x < s) red[threadIdx.x] |= red[threadIdx.x + s];
        __syncthreads();
    }
    if (threadIdx.x == 0) g_is64[slot] = (red[0] == 0) ? 1 : 0;
}

// ---------------- embedding gather (fp32 + split) ----------------------------
__global__ __launch_bounds__(128) void embed_kernel(
    const int* __restrict__ inp, const float* __restrict__ emb,
    __nv_bfloat16* __restrict__ AB) {
    int t = blockIdx.x;
    int tok = g_is64[0] ? inp[2 * t] : inp[t];
    int c = threadIdx.x * 4;
    float4 v = *(const float4*)(emb + (size_t)tok * E_ + c);
    *(float4*)(g_x + (size_t)t * E_ + c) = v;
    store_split2(AB, (size_t)t * KB3 + c, v.x, v.y);
    store_split2(AB, (size_t)t * KB3 + c + 2, v.z, v.w);
}

// ---------------- small SGEMM (head, N=128) ----------------------------------
template <int RELU>
__global__ __launch_bounds__(256) void sgemm_nt(
    const float* __restrict__ A, const float* __restrict__ B,
    const float* __restrict__ bias, float* __restrict__ C, int N, int K) {
    __shared__ float As[16][64];
    __shared__ float Bs[16][64];
    int tid = threadIdx.x;
    int tx = tid & 15, ty = tid >> 4;
    int m0 = blockIdx.y * 64, n0 = blockIdx.x * 64;
    int lr = tid >> 2;
    int lc = (tid & 3) * 4;
    const float* Ap = A + (size_t)(m0 + lr) * K + lc;
    const float* Bp = B + (size_t)(n0 + lr) * K + lc;
    float acc[4][4] = {};
    for (int k0 = 0; k0 < K; k0 += 16) {
        float4 a = *(const float4*)(Ap + k0);
        float4 b = *(const float4*)(Bp + k0);
        As[lc + 0][lr] = a.x; As[lc + 1][lr] = a.y; As[lc + 2][lr] = a.z; As[lc + 3][lr] = a.w;
        Bs[lc + 0][lr] = b.x; Bs[lc + 1][lr] = b.y; Bs[lc + 2][lr] = b.z; Bs[lc + 3][lr] = b.w;
        __syncthreads();
#pragma unroll
        for (int kk = 0; kk < 16; kk++) {
            float4 av = *(const float4*)&As[kk][ty * 4];
            float4 bv = *(const float4*)&Bs[kk][tx * 4];
            float ar[4] = {av.x, av.y, av.z, av.w};
            float br[4] = {bv.x, bv.y, bv.z, bv.w};
#pragma unroll
            for (int i = 0; i < 4; i++)
#pragma unroll
                for (int j = 0; j < 4; j++) acc[i][j] += ar[i] * br[j];
        }
        __syncthreads();
    }
    float b0 = bias[n0 + tx * 4 + 0];
    float b1 = bias[n0 + tx * 4 + 1];
    float b2 = bias[n0 + tx * 4 + 2];
    float b3 = bias[n0 + tx * 4 + 3];
#pragma unroll
    for (int i = 0; i < 4; i++) {
        float4 v;
        v.x = acc[i][0] + b0; v.y = acc[i][1] + b1;
        v.z = acc[i][2] + b2; v.w = acc[i][3] + b3;
        if (RELU) {
            v.x = fmaxf(v.x, 0.f); v.y = fmaxf(v.y, 0.f);
            v.z = fmaxf(v.z, 0.f); v.w = fmaxf(v.w, 0.f);
        }
        *(float4*)&C[(size_t)(m0 + ty * 4 + i) * N + n0 + tx * 4] = v;
    }
}

// ---------------- fused residual-add + layernorm (+split) --------------------
__global__ __launch_bounds__(128) void add_ln_kernel(
    const float* __restrict__ A, const float* __restrict__ R,
    const float* __restrict__ sc, const float* __restrict__ bi,
    float* __restrict__ out, __nv_bfloat16* __restrict__ AB) {
    __shared__ float red[4], red2[4];
    int t = blockIdx.x, tid = threadIdx.x;
    int e0 = tid * 4;
    float4 a = *(const float4*)&A[(size_t)t * E_ + e0];
    float4 r = *(const float4*)&R[(size_t)t * E_ + e0];
    float v0 = a.x + r.x, v1 = a.y + r.y, v2 = a.z + r.z, v3 = a.w + r.w;
    float sum = v0 + v1 + v2 + v3;
#pragma unroll
    for (int o = 16; o; o >>= 1) sum += __shfl_xor_sync(0xffffffffu, sum, o);
    int w = tid >> 5, lane = tid & 31;
    if (lane == 0) red[w] = sum;
    __syncthreads();
    sum = red[0] + red[1] + red[2] + red[3];
    float mu = sum * (1.f / E_);
    float d0 = v0 - mu, d1 = v1 - mu, d2 = v2 - mu, d3 = v3 - mu;
    float sq = d0 * d0 + d1 * d1 + d2 * d2 + d3 * d3;
#pragma unroll
    for (int o = 16; o; o >>= 1) sq += __shfl_xor_sync(0xffffffffu, sq, o);
    if (lane == 0) red2[w] = sq;
    __syncthreads();
    sq = red2[0] + red2[1] + red2[2] + red2[3];
    float rstd = rsqrtf(sq * (1.f / E_) + 1e-5f);
    float4 s4 = *(const float4*)&sc[e0];
    float4 b4 = *(const float4*)&bi[e0];
    float4 o4;
    o4.x = d0 * rstd * s4.x + b4.x;
    o4.y = d1 * rstd * s4.y + b4.y;
    o4.z = d2 * rstd * s4.z + b4.z;
    o4.w = d3 * rstd * s4.w + b4.w;
    *(float4*)&out[(size_t)t * E_ + e0] = o4;
    store_split2(AB, (size_t)t * KB3 + e0, o4.x, o4.y);
    store_split2(AB, (size_t)t * KB3 + e0 + 2, o4.z, o4.w);
}

// ---------------- loss ------------------------------------------------------
__global__ void zero_loss(float* p) { *p = 0.f; }

__global__ __launch_bounds__(256) void loss_kernel(
    const float* __restrict__ logits, const int* __restrict__ tgt,
    float* __restrict__ loss_out) {
    int warp = threadIdx.x >> 5, lane = threadIdx.x & 31;
    int t = blockIdx.x * 8 + warp;
    const float* lp = logits + (size_t)t * V_;
    float x[4];
    float mx = -1e30f, tot = 0.f;
#pragma unroll
    for (int i = 0; i < 4; i++) {
        x[i] = lp[lane + 32 * i];
        mx = fmaxf(mx, x[i]);
        tot += x[i];
    }
#pragma unroll
    for (int o = 16; o; o >>= 1) mx = fmaxf(mx, __shfl_xor_sync(0xffffffffu, mx, o));
    float s = 0.f;
#pragma unroll
    for (int i = 0; i < 4; i++) s += expf(x[i] - mx);
#pragma unroll
    for (int o = 16; o; o >>= 1) {
        s += __shfl_xor_sync(0xffffffffu, s, o);
        tot += __shfl_xor_sync(0xffffffffu, tot, o);
    }
    if (lane == 0) {
        float logZ = mx + logf(s);
        int tv = g_is64[1] ? tgt[2 * t] : tgt[t];
        float nll = logZ - lp[tv];
        float smooth = logZ - tot * (1.f / V_);
        atomicAdd(loss_out, ((1.f - EPS_) * nll + EPS_ * smooth) * (1.f / BT));
    }
}

// ---------------- driver -----------------------------------------------------
extern "C" void kernel_launch(void* const* d_in, const int* in_sizes, int n_in,
                              void* d_out, int out_size) {
    const int*   inputs  = (const int*)d_in[0];
    const int*   targets = (const int*)d_in[1];
    const float* emb     = (const float*)d_in[2];
    const float* qkv_w   = (const float*)d_in[3];
    const float* qkv_b   = (const float*)d_in[4];
    const float* aff1_w  = (const float*)d_in[5];
    const float* aff1_b  = (const float*)d_in[6];
    const float* aff2_w  = (const float*)d_in[7];
    const float* aff2_b  = (const float*)d_in[8];
    const float* ffn1_w  = (const float*)d_in[9];
    const float* ffn1_b  = (const float*)d_in[10];
    const float* ffn2_w  = (const float*)d_in[11];
    const float* ffn2_b  = (const float*)d_in[12];
    const float* ln1_s   = (const float*)d_in[13];
    const float* ln1_b   = (const float*)d_in[14];
    const float* ln2_s   = (const float*)d_in[15];
    const float* ln2_b   = (const float*)d_in[16];
    const float* head_w  = (const float*)d_in[17];
    const float* head_b  = (const float*)d_in[18];
    float* out = (float*)d_out;

    cudaFuncSetAttribute(gemm_mma<0, 0>, cudaFuncAttributeMaxDynamicSharedMemorySize, SMEM_MMA);
    cudaFuncSetAttribute(gemm_mma<1, 1>, cudaFuncAttributeMaxDynamicSharedMemorySize, SMEM_MMA);
    cudaFuncSetAttribute(gemm_mma<0, 2>, cudaFuncAttributeMaxDynamicSharedMemorySize, SMEM_MMA);
    cudaFuncSetAttribute(attn_mma, cudaFuncAttributeMaxDynamicSharedMemorySize, ATT_SMEM);

    float *px, *pqkv, *pb, *po1, *pvsuf;
    __nv_bfloat16 *ab1, *ab2, *pwqkv, *pw1, *pw2, *pw3, *pw4;
    __nv_bfloat16 *pqh, *pql, *pkh, *pkl, *pvh, *pvl;
    cudaGetSymbolAddress((void**)&px,   g_x);
    cudaGetSymbolAddress((void**)&pqkv, g_qkv);
    cudaGetSymbolAddress((void**)&pb,   g_b2);
    cudaGetSymbolAddress((void**)&po1,  g_o1);
    cudaGetSymbolAddress((void**)&ab1,  g_ab1);
    cudaGetSymbolAddress((void**)&ab2,  g_ab2);
    cudaGetSymbolAddress((void**)&pwqkv, g_wqkv);
    cudaGetSymbolAddress((void**)&pw1,  g_w1);
    cudaGetSymbolAddress((void**)&pw2,  g_w2);
    cudaGetSymbolAddress((void**)&pw3,  g_w3);
    cudaGetSymbolAddress((void**)&pw4,  g_w4);
    cudaGetSymbolAddress((void**)&pqh,  g_qh);
    cudaGetSymbolAddress((void**)&pql,  g_ql);
    cudaGetSymbolAddress((void**)&pkh,  g_kh);
    cudaGetSymbolAddress((void**)&pkl,  g_kl);
    cudaGetSymbolAddress((void**)&pvh,  g_vh);
    cudaGetSymbolAddress((void**)&pvl,  g_vl);
    cudaGetSymbolAddress((void**)&pvsuf, g_vsuf);

    detect_kernel<<<1, 256>>>(inputs, BT, 0);
    detect_kernel<<<1, 256>>>(targets, BT, 1);
    embed_kernel<<<BT, 128>>>(inputs, emb, ab1);

    conv_split_w<<<L_ * 1536, 128>>>(qkv_w,  pwqkv);
    conv_split_w<<<L_ * 512, 128>>>(aff1_w, pw1);
    conv_split_w<<<L_ * 512, 128>>>(aff2_w, pw2);
    conv_split_w<<<L_ * 512, 128>>>(ffn1_w, pw3);
    conv_split_w<<<L_ * 512, 128>>>(ffn2_w, pw4);

    for (int l = 0; l < L_; l++) {
        // qkv: ab1 -> attention head planes (fused split epilogue)
        gemm_mma<0, 2><<<dim3(12, 32), 256, SMEM_MMA>>>(
            ab1, pwqkv + (size_t)l * 1536 * KB3, qkv_b + (size_t)l * 1536,
            nullptr, nullptr, pqh, pql, pkh, pkl, pvh, pvl, 1536);
        vsuf_kernel<<<32, 64>>>(pvh, pvl, pvsuf);
        attn_mma<<<dim3(16, 32), 128, ATT_SMEM>>>(pqh, pql, pkh, pkl, pvh, pvl,
                                                  pvsuf, ab2);
        // aff1: ab2 -> ab1 (split, relu)
        gemm_mma<1, 1><<<dim3(4, 32), 256, SMEM_MMA>>>(
            ab2, pw1 + (size_t)l * 512 * KB3, aff1_b + (size_t)l * 512,
            nullptr, ab1, nullptr, nullptr, nullptr, nullptr, nullptr, nullptr, 512);
        // aff2: ab1 -> pb (fp32)
        gemm_mma<0, 0><<<dim3(4, 32), 256, SMEM_MMA>>>(
            ab1, pw2 + (size_t)l * 512 * KB3, aff2_b + (size_t)l * 512,
            pb, nullptr, nullptr, nullptr, nullptr, nullptr, nullptr, nullptr, 512);
        // ln1: pb+px -> po1 fp32 + ab2 split
        add_ln_kernel<<<BT, 128>>>(pb, px, ln1_s + (size_t)l * 512,
                                   ln1_b + (size_t)l * 512, po1, ab2);
        // ffn1: ab2 -> ab1 (split, relu)
        gemm_mma<1, 1><<<dim3(4, 32), 256, SMEM_MMA>>>(
            ab2, pw3 + (size_t)l * 512 * KB3, ffn1_b + (size_t)l * 512,
            nullptr, ab1, nullptr, nullptr, nullptr, nullptr, nullptr, nullptr, 512);
        // ffn2: ab1 -> pb (fp32)
        gemm_mma<0, 0><<<dim3(4, 32), 256, SMEM_MMA>>>(
            ab1, pw4 + (size_t)l * 512 * KB3, ffn2_b + (size_t)l * 512,
            pb, nullptr, nullptr, nullptr, nullptr, nullptr, nullptr, nullptr, 512);
        // ln2: po1+pb -> px fp32 + ab1 split
        add_ln_kernel<<<BT, 128>>>(po1, pb, ln2_s + (size_t)l * 512,
                                   ln2_b + (size_t)l * 512, px, ab1);
    }

    float* logits_dst = (out_size >= BT * V_) ? out : pqkv;
    sgemm_nt<0><<<dim3(2, 64), 256>>>(px, head_w, head_b, logits_dst, V_, 512);

    float* loss_dst = nullptr;
    if (out_size > BT * V_) loss_dst = out + BT * V_;
    else if (out_size < BT * V_ && out_size >= 1) loss_dst = out;
    if (loss_dst) {
        zero_loss<<<1, 1>>>(loss_dst);
        loss_kernel<<<BT / 8, 256>>>(logits_dst, targets, loss_dst);
    }
}

// round 14
// speedup vs baseline: 1.1654x; 1.1654x over previous
#include <cuda_runtime.h>
#include <cuda_bf16.h>
#include <cstdint>

#define BT 4096
#define T_ 1024
#define E_ 512
#define H_ 8
#define L_ 8
#define V_ 128
#define EPS_ 0.1f
#define KB 1024   // [hi|lo] split width

// ---------------- scratch (device globals) ----------------------------------
__device__ float g_x[BT * E_];
__device__ float g_qkv[BT * 3 * E_];   // logits fallback scratch only
__device__ float g_b2[BT * E_];
__device__ float g_o1[BT * E_];
__device__ int   g_is64[2];

__device__ __nv_bfloat16 g_ab1[BT * KB];
__device__ __nv_bfloat16 g_ab2[BT * KB];
__device__ __nv_bfloat16 g_wqkv[L_ * 1536 * KB];
__device__ __nv_bfloat16 g_w1[L_ * 512 * KB];
__device__ __nv_bfloat16 g_w2[L_ * 512 * KB];
__device__ __nv_bfloat16 g_w3[L_ * 512 * KB];
__device__ __nv_bfloat16 g_w4[L_ * 512 * KB];

__device__ __nv_bfloat16 g_qh[32 * 1024 * 64];
__device__ __nv_bfloat16 g_ql[32 * 1024 * 64];
__device__ __nv_bfloat16 g_kh[32 * 1024 * 64];
__device__ __nv_bfloat16 g_kl[32 * 1024 * 64];
__device__ __nv_bfloat16 g_vh[32 * 1024 * 64];
__device__ __nv_bfloat16 g_vl[32 * 1024 * 64];
__device__ float g_vsuf[32 * 17 * 64];

// ---------------- PTX helpers ------------------------------------------------
#define SW128(o) ((o) ^ (((o) >> 3) & 0x70))
#define CP_ASYNC16(dst, src) \
    asm volatile("cp.async.cg.shared.global [%0], [%1], 16;" :: "r"(dst), "l"(src))
#define CP_COMMIT() asm volatile("cp.async.commit_group;" ::: "memory")
#define CP_WAIT1() asm volatile("cp.async.wait_group 1;" ::: "memory")
#define CP_WAIT0() asm volatile("cp.async.wait_group 0;" ::: "memory")

#define LDMATRIX_X4(r0, r1, r2, r3, addr)                                      \
    asm volatile("ldmatrix.sync.aligned.m8n8.x4.shared.b16 {%0,%1,%2,%3}, [%4];" \
                 : "=r"(r0), "=r"(r1), "=r"(r2), "=r"(r3) : "r"(addr))

#define LDMATRIX_X4T(r0, r1, r2, r3, addr)                                     \
    asm volatile("ldmatrix.sync.aligned.m8n8.x4.trans.shared.b16 {%0,%1,%2,%3}, [%4];" \
                 : "=r"(r0), "=r"(r1), "=r"(r2), "=r"(r3) : "r"(addr))

#define MMA16816(d, a, b0, b1)                                                 \
    asm volatile("mma.sync.aligned.m16n8k16.row.col.f32.bf16.bf16.f32 "        \
                 "{%0,%1,%2,%3}, {%4,%5,%6,%7}, {%8,%9}, {%0,%1,%2,%3};"       \
                 : "+f"((d)[0]), "+f"((d)[1]), "+f"((d)[2]), "+f"((d)[3])      \
                 : "r"((a)[0]), "r"((a)[1]), "r"((a)[2]), "r"((a)[3]),         \
                   "r"(b0), "r"(b1))

__device__ __forceinline__ uint32_t pack_hi_res(float a, float b, float& ra, float& rb) {
    __nv_bfloat16 h0 = __float2bfloat16(a), h1 = __float2bfloat16(b);
    ra = a - __bfloat162float(h0);
    rb = b - __bfloat162float(h1);
    return ((uint32_t)__bfloat16_as_ushort(h1) << 16) | (uint32_t)__bfloat16_as_ushort(h0);
}
__device__ __forceinline__ uint32_t pack2bf(float a, float b) {
    __nv_bfloat162 t = __floats2bfloat162_rn(a, b);
    return *reinterpret_cast<uint32_t*>(&t);
}
// split store into [hi|lo] activation buffer (KB=1024 row width)
__device__ __forceinline__ void store_hl2(__nv_bfloat16* ab, size_t row, int col,
                                          float a, float b) {
    __nv_bfloat16 h0 = __float2bfloat16(a), h1 = __float2bfloat16(b);
    __nv_bfloat162 hh, ll;
    hh.x = h0; hh.y = h1;
    ll.x = __float2bfloat16(a - __bfloat162float(h0));
    ll.y = __float2bfloat16(b - __bfloat162float(h1));
    *(__nv_bfloat162*)&ab[row * KB + col] = hh;
    *(__nv_bfloat162*)&ab[row * KB + col + 512] = ll;
}
__device__ __forceinline__ void store_plane2(__nv_bfloat16* hp, __nv_bfloat16* lp,
                                             size_t dst, float a, float b) {
    __nv_bfloat16 h0 = __float2bfloat16(a), h1 = __float2bfloat16(b);
    __nv_bfloat162 hh, ll;
    hh.x = h0; hh.y = h1;
    ll.x = __float2bfloat16(a - __bfloat162float(h0));
    ll.y = __float2bfloat16(b - __bfloat162float(h1));
    *(__nv_bfloat162*)&hp[dst] = hh;
    *(__nv_bfloat162*)&lp[dst] = ll;
}

// ---------------- weight split conversion: [hi|lo] ---------------------------
__global__ __launch_bounds__(128) void conv_split_w(
    const float* __restrict__ X, __nv_bfloat16* __restrict__ O) {
    size_t r = blockIdx.x;
    int c = threadIdx.x * 4;
    float4 v = *(const float4*)&X[r * 512 + c];
    float f[4] = {v.x, v.y, v.z, v.w};
    __nv_bfloat16 h[4], lo[4];
#pragma unroll
    for (int i = 0; i < 4; i++) {
        h[i] = __float2bfloat16(f[i]);
        lo[i] = __float2bfloat16(f[i] - __bfloat162float(h[i]));
    }
    __nv_bfloat16* o = O + r * KB + c;
    __nv_bfloat162 h01, h23, l01, l23;
    h01.x = h[0]; h01.y = h[1]; h23.x = h[2]; h23.y = h[3];
    l01.x = lo[0]; l01.y = lo[1]; l23.x = lo[2]; l23.y = lo[3];
    *(__nv_bfloat162*)&o[0] = h01;
    *(__nv_bfloat162*)&o[2] = h23;
    *(__nv_bfloat162*)&o[512] = l01;
    *(__nv_bfloat162*)&o[514] = l23;
}

// ---------------- V suffix sums from planes ----------------------------------
__global__ __launch_bounds__(64) void vsuf_kernel(
    const __nv_bfloat16* __restrict__ vh, const __nv_bfloat16* __restrict__ vl,
    float* __restrict__ vsuf) {
    int bh = blockIdx.x, d = threadIdx.x;
    float s = 0.f;
    vsuf[((size_t)bh * 17 + 16) * 64 + d] = 0.f;
    for (int jt = 15; jt >= 0; jt--) {
        const __nv_bfloat16* ph = vh + ((size_t)bh * 1024 + jt * 64) * 64 + d;
        const __nv_bfloat16* pl = vl + ((size_t)bh * 1024 + jt * 64) * 64 + d;
#pragma unroll 4
        for (int t = 0; t < 64; t++)
            s += __bfloat162float(ph[(size_t)t * 64]) + __bfloat162float(pl[(size_t)t * 64]);
        vsuf[((size_t)bh * 17 + jt) * 64 + d] = s;
    }
}

// ---------------- tensor-core flash attention --------------------------------
#define ATT_SMEM 81920
#define AQH 0
#define AQL 8192
#define AST(s) (16384 + (s) * 32768)

__device__ __forceinline__ void att_load_kv(
    uint32_t sb, int stage, size_t base,
    const __nv_bfloat16* kh, const __nv_bfloat16* kl,
    const __nv_bfloat16* vh, const __nv_bfloat16* vl, int kt, int tid) {
    uint32_t st = sb + AST(stage);
#pragma unroll
    for (int i = 0; i < 4; i++) {
        int g = i * 128 + tid, r = g >> 3, seg = g & 7;
        uint32_t off = SW128(r * 128 + seg * 16);
        size_t so = (base + (size_t)(kt * 64 + r) * 64) * 2 + seg * 16;
        CP_ASYNC16(st + off,         (const char*)kh + so);
        CP_ASYNC16(st + 8192 + off,  (const char*)kl + so);
        CP_ASYNC16(st + 16384 + off, (const char*)vh + so);
        CP_ASYNC16(st + 24576 + off, (const char*)vl + so);
    }
    CP_COMMIT();
}

__global__ __launch_bounds__(128) void attn_mma(
    const __nv_bfloat16* __restrict__ qh, const __nv_bfloat16* __restrict__ ql,
    const __nv_bfloat16* __restrict__ kh, const __nv_bfloat16* __restrict__ kl,
    const __nv_bfloat16* __restrict__ vh, const __nv_bfloat16* __restrict__ vl,
    const float* __restrict__ vsuf, __nv_bfloat16* __restrict__ AB) {
    extern __shared__ char sm[];
    uint32_t sb = (uint32_t)__cvta_generic_to_shared(sm);
    int tid = threadIdx.x, wid = tid >> 5, lane = tid & 31;
    int qt = blockIdx.x, bh = blockIdx.y;
    int b = bh >> 3, h = bh & 7;
    size_t base = (size_t)bh * 1024 * 64;
    int q0 = qt * 64;
    int g = lane >> 2, qd = lane & 3;

#pragma unroll
    for (int i = 0; i < 4; i++) {
        int gg = i * 128 + tid, r = gg >> 3, seg = gg & 7;
        uint32_t off = SW128(r * 128 + seg * 16);
        size_t so = (base + (size_t)(q0 + r) * 64) * 2 + seg * 16;
        CP_ASYNC16(sb + AQH + off, (const char*)qh + so);
        CP_ASYNC16(sb + AQL + off, (const char*)ql + so);
    }
    CP_COMMIT();
    att_load_kv(sb, 0, base, kh, kl, vh, vl, 0, tid);

    float Oa[8][4];
#pragma unroll
    for (int j = 0; j < 8; j++)
#pragma unroll
        for (int e = 0; e < 4; e++) Oa[j][e] = 0.f;
    float mrow0 = 0.f, mrow1 = 0.f, lrow0 = 0.f, lrow1 = 0.f;

    int qA = q0 + wid * 16 + g, qB = qA + 8;
    uint32_t arow = (uint32_t)(wid * 16 + (lane & 15));
    uint32_t acb = (uint32_t)((lane >> 4) << 4);
    int bq = lane >> 3, br = lane & 7;
    uint32_t brbase = (uint32_t)(((bq >> 1) << 3) + br);
    uint32_t bcb = (uint32_t)((bq & 1) << 4);
    uint32_t vrow = (uint32_t)(((lane >> 3) & 1) * 8 + (lane & 7));
    uint32_t vcb = (uint32_t)((lane >> 4) << 4);

    for (int kt = 0; kt <= qt; kt++) {
        if (kt < qt) att_load_kv(sb, (kt + 1) & 1, base, kh, kl, vh, vl, kt + 1, tid);
        if (kt < qt) { CP_WAIT1(); } else { CP_WAIT0(); }
        __syncthreads();
        uint32_t st = sb + AST(kt & 1);

        float Sf[8][4];
#pragma unroll
        for (int j = 0; j < 8; j++)
#pragma unroll
            for (int e = 0; e < 4; e++) Sf[j][e] = 0.f;
#pragma unroll
        for (int ks = 0; ks < 12; ks++) {
            int grp = ks >> 2, kk2 = ks & 3;
            uint32_t qpl = sb + (grp == 1 ? AQL : AQH);
            uint32_t kpl = st + (grp == 2 ? 8192u : 0u);
            uint32_t af[4];
            LDMATRIX_X4(af[0], af[1], af[2], af[3],
                        qpl + SW128(arow * 128 + kk2 * 32 + acb));
#pragma unroll
            for (int np = 0; np < 4; np++) {
                uint32_t bf[4];
                uint32_t boff = SW128((np * 16 + brbase) * 128 + kk2 * 32 + bcb);
                LDMATRIX_X4(bf[0], bf[1], bf[2], bf[3], kpl + boff);
                MMA16816(Sf[2 * np], af, bf[0], bf[1]);
                MMA16816(Sf[2 * np + 1], af, bf[2], bf[3]);
            }
        }

        bool diag = (kt == qt);
        float tm0 = -1e30f, tm1 = -1e30f;
#pragma unroll
        for (int j = 0; j < 8; j++) {
            int k0 = kt * 64 + j * 8 + qd * 2;
            float s0 = Sf[j][0] * 0.125f, s1 = Sf[j][1] * 0.125f;
            float s2 = Sf[j][2] * 0.125f, s3 = Sf[j][3] * 0.125f;
            if (diag) {
                if (k0 > qA) s0 = 0.f;
                if (k0 + 1 > qA) s1 = 0.f;
                if (k0 > qB) s2 = 0.f;
                if (k0 + 1 > qB) s3 = 0.f;
            }
            Sf[j][0] = s0; Sf[j][1] = s1; Sf[j][2] = s2; Sf[j][3] = s3;
            tm0 = fmaxf(tm0, fmaxf(s0, s1));
            tm1 = fmaxf(tm1, fmaxf(s2, s3));
        }
        tm0 = fmaxf(tm0, __shfl_xor_sync(0xffffffffu, tm0, 1));
        tm0 = fmaxf(tm0, __shfl_xor_sync(0xffffffffu, tm0, 2));
        tm1 = fmaxf(tm1, __shfl_xor_sync(0xffffffffu, tm1, 1));
        tm1 = fmaxf(tm1, __shfl_xor_sync(0xffffffffu, tm1, 2));
        float mn0 = fmaxf(mrow0, tm0), mn1 = fmaxf(mrow1, tm1);
        float al0 = __expf(mrow0 - mn0), al1 = __expf(mrow1 - mn1);
        mrow0 = mn0; mrow1 = mn1;
        float ps0 = 0.f, ps1 = 0.f;
#pragma unroll
        for (int j = 0; j < 8; j++) {
            float p0 = __expf(Sf[j][0] - mn0), p1 = __expf(Sf[j][1] - mn0);
            float p2 = __expf(Sf[j][2] - mn1), p3 = __expf(Sf[j][3] - mn1);
            Sf[j][0] = p0; Sf[j][1] = p1; Sf[j][2] = p2; Sf[j][3] = p3;
            ps0 += p0 + p1; ps1 += p2 + p3;
            Oa[j][0] *= al0; Oa[j][1] *= al0; Oa[j][2] *= al1; Oa[j][3] *= al1;
        }
        ps0 += __shfl_xor_sync(0xffffffffu, ps0, 1);
        ps0 += __shfl_xor_sync(0xffffffffu, ps0, 2);
        ps1 += __shfl_xor_sync(0xffffffffu, ps1, 1);
        ps1 += __shfl_xor_sync(0xffffffffu, ps1, 2);
        lrow0 = lrow0 * al0 + ps0;
        lrow1 = lrow1 * al1 + ps1;

#pragma unroll
        for (int kk = 0; kk < 4; kk++) {
            int j0 = 2 * kk, j1 = 2 * kk + 1;
            float r0, r1;
            uint32_t ah[4], alr[4];
            ah[0] = pack_hi_res(Sf[j0][0], Sf[j0][1], r0, r1); alr[0] = pack2bf(r0, r1);
            ah[1] = pack_hi_res(Sf[j0][2], Sf[j0][3], r0, r1); alr[1] = pack2bf(r0, r1);
            ah[2] = pack_hi_res(Sf[j1][0], Sf[j1][1], r0, r1); alr[2] = pack2bf(r0, r1);
            ah[3] = pack_hi_res(Sf[j1][2], Sf[j1][3], r0, r1); alr[3] = pack2bf(r0, r1);
#pragma unroll
            for (int dg = 0; dg < 4; dg++) {
                uint32_t voff = SW128((kk * 16 + vrow) * 128 + dg * 32 + vcb);
                uint32_t vh0, vh1, vh2, vh3, vl0, vl1, vl2, vl3;
                LDMATRIX_X4T(vh0, vh1, vh2, vh3, st + 16384 + voff);
                LDMATRIX_X4T(vl0, vl1, vl2, vl3, st + 24576 + voff);
                MMA16816(Oa[2 * dg], ah, vh0, vh1);
                MMA16816(Oa[2 * dg], alr, vh0, vh1);
                MMA16816(Oa[2 * dg], ah, vl0, vl1);
                MMA16816(Oa[2 * dg + 1], ah, vh2, vh3);
                MMA16816(Oa[2 * dg + 1], alr, vh2, vh3);
                MMA16816(Oa[2 * dg + 1], ah, vl2, vl3);
            }
        }
        __syncthreads();
    }

    float wf0 = __expf(-mrow0), wf1 = __expf(-mrow1);
    float nfut = (float)(1024 - (qt + 1) * 64);
    float inv0 = 1.f / (lrow0 + wf0 * nfut);
    float inv1 = 1.f / (lrow1 + wf1 * nfut);
    const float* vs = vsuf + ((size_t)bh * 17 + qt + 1) * 64;
    size_t rowA = (size_t)b * 1024 + qA;
    size_t rowB = rowA + 8;
#pragma unroll
    for (int j = 0; j < 8; j++) {
        int d = j * 8 + qd * 2;
        float v0 = vs[d], v1 = vs[d + 1];
        int col = h * 64 + d;
        store_hl2(AB, rowA, col, (Oa[j][0] + wf0 * v0) * inv0,
                  (Oa[j][1] + wf0 * v1) * inv0);
        store_hl2(AB, rowB, col, (Oa[j][2] + wf1 * v0) * inv1,
                  (Oa[j][3] + wf1 * v1) * inv1);
    }
}

// ---------------- mma.sync GEMM, [hi|lo] operands, fused epilogues -----------
// logical K chunks c=0..23 remap: A: c<16?c:c-16   B: c<8?c:c-8
// OUT=0: fp32 +bias(+relu)  OUT=1: split [hi|lo] act buffer  OUT=2: qkv planes
#define STAGE_BYTES 32768
#define SMEM_MMA (3 * STAGE_BYTES)
#define NCHUNK 24
#define EPIPITCH 132

__device__ __forceinline__ void mma_load_chunk(
    uint32_t sbase, int stage,
    const __nv_bfloat16* A, const __nv_bfloat16* Bw,
    int m0, int n0, int c, int tid) {
    uint32_t abase = sbase + stage * STAGE_BYTES;
    uint32_t bbase = abase + 16384;
    int aoff = ((c < 16) ? c : c - 16) * 128;
    int boff = ((c < 8) ? c : c - 8) * 128;
#pragma unroll
    for (int i = 0; i < 4; i++) {
        int g = i * 256 + tid, row = g >> 3, seg = g & 7;
        uint32_t dst = abase + SW128(row * 128 + seg * 16);
        const char* src = (const char*)A + (size_t)(m0 + row) * 2048 + aoff + seg * 16;
        CP_ASYNC16(dst, src);
    }
#pragma unroll
    for (int i = 0; i < 4; i++) {
        int g = i * 256 + tid, row = g >> 3, seg = g & 7;
        uint32_t dst = bbase + SW128(row * 128 + seg * 16);
        const char* src = (const char*)Bw + (size_t)(n0 + row) * 2048 + boff + seg * 16;
        CP_ASYNC16(dst, src);
    }
    CP_COMMIT();
}

template <int RELU, int OUT>
__global__ __launch_bounds__(256) void gemm_mma(
    const __nv_bfloat16* __restrict__ A, const __nv_bfloat16* __restrict__ Bw,
    const float* __restrict__ bias, float* __restrict__ C,
    __nv_bfloat16* __restrict__ AB,
    __nv_bfloat16* __restrict__ qh, __nv_bfloat16* __restrict__ ql,
    __nv_bfloat16* __restrict__ kh, __nv_bfloat16* __restrict__ kl,
    __nv_bfloat16* __restrict__ vh, __nv_bfloat16* __restrict__ vl,
    int N) {
    extern __shared__ char smem[];
    uint32_t sbase = (uint32_t)__cvta_generic_to_shared(smem);
    int tid = threadIdx.x, wid = tid >> 5, lane = tid & 31;
    int m0 = blockIdx.y * 128, n0 = blockIdx.x * 128;
    int warp_m = wid & 3, warp_n = wid >> 2;

    float acc[2][8][4];
#pragma unroll
    for (int mt = 0; mt < 2; mt++)
#pragma unroll
        for (int nt = 0; nt < 8; nt++)
#pragma unroll
            for (int e = 0; e < 4; e++) acc[mt][nt][e] = 0.f;

    mma_load_chunk(sbase, 0, A, Bw, m0, n0, 0, tid);
    mma_load_chunk(sbase, 1, A, Bw, m0, n0, 1, tid);

    int a_row = warp_m * 32 + (lane & 15);
    int a_col8 = (lane >> 4) << 3;
    int bq = lane >> 3, br = lane & 7;
    int b_n = warp_n * 64 + ((bq >> 1) << 3) + br;
    int b_col8 = (bq & 1) << 3;

    for (int c = 0; c < NCHUNK; c++) {
        if (c + 1 < NCHUNK) { CP_WAIT1(); } else { CP_WAIT0(); }
        __syncthreads();
        if (c + 2 < NCHUNK)
            mma_load_chunk(sbase, (c + 2) % 3, A, Bw, m0, n0, c + 2, tid);

        uint32_t abase = sbase + (c % 3) * STAGE_BYTES;
        uint32_t bbase = abase + 16384;
#pragma unroll
        for (int ks = 0; ks < 4; ks++) {
            uint32_t af[2][4];
#pragma unroll
            for (int mt = 0; mt < 2; mt++) {
                uint32_t off = (uint32_t)((a_row + mt * 16) * 128 + (ks * 16 + a_col8) * 2);
                LDMATRIX_X4(af[mt][0], af[mt][1], af[mt][2], af[mt][3],
                            abase + SW128(off));
            }
#pragma unroll
            for (int np = 0; np < 4; np++) {
                uint32_t bf[4];
                uint32_t off = (uint32_t)((b_n + np * 16) * 128 + (ks * 16 + b_col8) * 2);
                LDMATRIX_X4(bf[0], bf[1], bf[2], bf[3], bbase + SW128(off));
#pragma unroll
                for (int mt = 0; mt < 2; mt++) {
                    MMA16816(acc[mt][2 * np], af[mt], bf[0], bf[1]);
                    MMA16816(acc[mt][2 * np + 1], af[mt], bf[2], bf[3]);
                }
            }
        }
    }

    int g = lane >> 2, q = lane & 3;
    if (OUT == 0) {
#pragma unroll
        for (int mt = 0; mt < 2; mt++) {
            int row0 = m0 + warp_m * 32 + mt * 16 + g;
#pragma unroll
            for (int nt = 0; nt < 8; nt++) {
                int col = n0 + warp_n * 64 + nt * 8 + q * 2;
                float b0 = bias[col], b1 = bias[col + 1];
                float v0 = acc[mt][nt][0] + b0, v1 = acc[mt][nt][1] + b1;
                float v2 = acc[mt][nt][2] + b0, v3 = acc[mt][nt][3] + b1;
                if (RELU) {
                    v0 = fmaxf(v0, 0.f); v1 = fmaxf(v1, 0.f);
                    v2 = fmaxf(v2, 0.f); v3 = fmaxf(v3, 0.f);
                }
                *(float2*)&C[(size_t)row0 * N + col] = make_float2(v0, v1);
                *(float2*)&C[(size_t)(row0 + 8) * N + col] = make_float2(v2, v3);
            }
        }
    } else {
        // stage post-bias fp32 tile in smem, then coalesced split-bf16 stores
        float* sred = (float*)smem;
        __syncthreads();  // all warps done reading pipeline smem
#pragma unroll
        for (int mt = 0; mt < 2; mt++) {
            int r0 = warp_m * 32 + mt * 16 + g;
#pragma unroll
            for (int nt = 0; nt < 8; nt++) {
                int col = warp_n * 64 + nt * 8 + q * 2;
                float b0 = bias[n0 + col], b1 = bias[n0 + col + 1];
                float v0 = acc[mt][nt][0] + b0, v1 = acc[mt][nt][1] + b1;
                float v2 = acc[mt][nt][2] + b0, v3 = acc[mt][nt][3] + b1;
                if (RELU) {
                    v0 = fmaxf(v0, 0.f); v1 = fmaxf(v1, 0.f);
                    v2 = fmaxf(v2, 0.f); v3 = fmaxf(v3, 0.f);
                }
                *(float2*)&sred[r0 * EPIPITCH + col] = make_float2(v0, v1);
                *(float2*)&sred[(r0 + 8) * EPIPITCH + col] = make_float2(v2, v3);
            }
        }
        __syncthreads();
#pragma unroll
        for (int it = 0; it < 32; it++) {
            int p = it * 256 + tid;        // 0..8191 = 128 rows x 64 col-pairs
            int row = p >> 6, cp = p & 63;
            int col = cp * 2;
            float v0 = sred[row * EPIPITCH + col];
            float v1 = sred[row * EPIPITCH + col + 1];
            int token = m0 + row;
            if (OUT == 1) {
                store_hl2(AB, (size_t)token, n0 + col, v0, v1);
            } else {
                int cg = n0 + col;
                int h = cg / 192, r = cg - h * 192;
                int typ = r >> 6, d = r & 63;
                __nv_bfloat16* hp = (typ == 0) ? qh : (typ == 1) ? kh : vh;
                __nv_bfloat16* lp = (typ == 0) ? ql : (typ == 1) ? kl : vl;
                int bb = token >> 10, t = token & 1023;
                size_t dst = ((size_t)(bb * 8 + h) * 1024 + t) * 64 + d;
                store_plane2(hp, lp, dst, v0, v1);
            }
        }
    }
}

// ---------------- int64-vs-int32 detection ----------------------------------
__global__ void detect_kernel(const int* __restrict__ p, int n, int slot) {
    __shared__ int red[256];
    int acc = 0;
    for (int j = 2 * threadIdx.x + 1; j < n; j += 512) acc |= p[j];
    red[threadIdx.x] = acc;
    __syncthreads();
    for (int s = 128; s > 0; s >>= 1) {
        if (threadIdx.x < s) red[threadIdx.x] |= red[threadIdx.x + s];
        __syncthreads();
    }
    if (threadIdx.x == 0) g_is64[slot] = (red[0] == 0) ? 1 : 0;
}

// ---------------- embedding gather (fp32 + split) ----------------------------
__global__ __launch_bounds__(128) void embed_kernel(
    const int* __restrict__ inp, const float* __restrict__ emb,
    __nv_bfloat16* __restrict__ AB) {
    int t = blockIdx.x;
    int tok = g_is64[0] ? inp[2 * t] : inp[t];
    int c = threadIdx.x * 4;
    float4 v = *(const float4*)(emb + (size_t)tok * E_ + c);
    *(float4*)(g_x + (size_t)t * E_ + c) = v;
    store_hl2(AB, (size_t)t, c, v.x, v.y);
    store_hl2(AB, (size_t)t, c + 2, v.z, v.w);
}

// ---------------- small SGEMM (head, N=128) ----------------------------------
template <int RELU>
__global__ __launch_bounds__(256) void sgemm_nt(
    const float* __restrict__ A, const float* __restrict__ B,
    const float* __restrict__ bias, float* __restrict__ C, int N, int K) {
    __shared__ float As[16][64];
    __shared__ float Bs[16][64];
    int tid = threadIdx.x;
    int tx = tid & 15, ty = tid >> 4;
    int m0 = blockIdx.y * 64, n0 = blockIdx.x * 64;
    int lr = tid >> 2;
    int lc = (tid & 3) * 4;
    const float* Ap = A + (size_t)(m0 + lr) * K + lc;
    const float* Bp = B + (size_t)(n0 + lr) * K + lc;
    float acc[4][4] = {};
    for (int k0 = 0; k0 < K; k0 += 16) {
        float4 a = *(const float4*)(Ap + k0);
        float4 b = *(const float4*)(Bp + k0);
        As[lc + 0][lr] = a.x; As[lc + 1][lr] = a.y; As[lc + 2][lr] = a.z; As[lc + 3][lr] = a.w;
        Bs[lc + 0][lr] = b.x; Bs[lc + 1][lr] = b.y; Bs[lc + 2][lr] = b.z; Bs[lc + 3][lr] = b.w;
        __syncthreads();
#pragma unroll
        for (int kk = 0; kk < 16; kk++) {
            float4 av = *(const float4*)&As[kk][ty * 4];
            float4 bv = *(const float4*)&Bs[kk][tx * 4];
            float ar[4] = {av.x, av.y, av.z, av.w};
            float br[4] = {bv.x, bv.y, bv.z, bv.w};
#pragma unroll
            for (int i = 0; i < 4; i++)
#pragma unroll
                for (int j = 0; j < 4; j++) acc[i][j] += ar[i] * br[j];
        }
        __syncthreads();
    }
    float b0 = bias[n0 + tx * 4 + 0];
    float b1 = bias[n0 + tx * 4 + 1];
    float b2 = bias[n0 + tx * 4 + 2];
    float b3 = bias[n0 + tx * 4 + 3];
#pragma unroll
    for (int i = 0; i < 4; i++) {
        float4 v;
        v.x = acc[i][0] + b0; v.y = acc[i][1] + b1;
        v.z = acc[i][2] + b2; v.w = acc[i][3] + b3;
        if (RELU) {
            v.x = fmaxf(v.x, 0.f); v.y = fmaxf(v.y, 0.f);
            v.z = fmaxf(v.z, 0.f); v.w = fmaxf(v.w, 0.f);
        }
        *(float4*)&C[(size_t)(m0 + ty * 4 + i) * N + n0 + tx * 4] = v;
    }
}

// ---------------- fused residual-add + layernorm (+split) --------------------
__global__ __launch_bounds__(128) void add_ln_kernel(
    const float* __restrict__ A, const float* __restrict__ R,
    const float* __restrict__ sc, const float* __restrict__ bi,
    float* __restrict__ out, __nv_bfloat16* __restrict__ AB) {
    __shared__ float red[4], red2[4];
    int t = blockIdx.x, tid = threadIdx.x;
    int e0 = tid * 4;
    float4 a = *(const float4*)&A[(size_t)t * E_ + e0];
    float4 r = *(const float4*)&R[(size_t)t * E_ + e0];
    float v0 = a.x + r.x, v1 = a.y + r.y, v2 = a.z + r.z, v3 = a.w + r.w;
    float sum = v0 + v1 + v2 + v3;
#pragma unroll
    for (int o = 16; o; o >>= 1) sum += __shfl_xor_sync(0xffffffffu, sum, o);
    int w = tid >> 5, lane = tid & 31;
    if (lane == 0) red[w] = sum;
    __syncthreads();
    sum = red[0] + red[1] + red[2] + red[3];
    float mu = sum * (1.f / E_);
    float d0 = v0 - mu, d1 = v1 - mu, d2 = v2 - mu, d3 = v3 - mu;
    float sq = d0 * d0 + d1 * d1 + d2 * d2 + d3 * d3;
#pragma unroll
    for (int o = 16; o; o >>= 1) sq += __shfl_xor_sync(0xffffffffu, sq, o);
    if (lane == 0) red2[w] = sq;
    __syncthreads();
    sq = red2[0] + red2[1] + red2[2] + red2[3];
    float rstd = rsqrtf(sq * (1.f / E_) + 1e-5f);
    float4 s4 = *(const float4*)&sc[e0];
    float4 b4 = *(const float4*)&bi[e0];
    float4 o4;
    o4.x = d0 * rstd * s4.x + b4.x;
    o4.y = d1 * rstd * s4.y + b4.y;
    o4.z = d2 * rstd * s4.z + b4.z;
    o4.w = d3 * rstd * s4.w + b4.w;
    *(float4*)&out[(size_t)t * E_ + e0] = o4;
    store_hl2(AB, (size_t)t, e0, o4.x, o4.y);
    store_hl2(AB, (size_t)t, e0 + 2, o4.z, o4.w);
}

// ---------------- loss ------------------------------------------------------
__global__ void zero_loss(float* p) { *p = 0.f; }

__global__ __launch_bounds__(256) void loss_kernel(
    const float* __restrict__ logits, const int* __restrict__ tgt,
    float* __restrict__ loss_out) {
    int warp = threadIdx.x >> 5, lane = threadIdx.x & 31;
    int t = blockIdx.x * 8 + warp;
    const float* lp = logits + (size_t)t * V_;
    float x[4];
    float mx = -1e30f, tot = 0.f;
#pragma unroll
    for (int i = 0; i < 4; i++) {
        x[i] = lp[lane + 32 * i];
        mx = fmaxf(mx, x[i]);
        tot += x[i];
    }
#pragma unroll
    for (int o = 16; o; o >>= 1) mx = fmaxf(mx, __shfl_xor_sync(0xffffffffu, mx, o));
    float s = 0.f;
#pragma unroll
    for (int i = 0; i < 4; i++) s += expf(x[i] - mx);
#pragma unroll
    for (int o = 16; o; o >>= 1) {
        s += __shfl_xor_sync(0xffffffffu, s, o);
        tot += __shfl_xor_sync(0xffffffffu, tot, o);
    }
    if (lane == 0) {
        float logZ = mx + logf(s);
        int tv = g_is64[1] ? tgt[2 * t] : tgt[t];
        float nll = logZ - lp[tv];
        float smooth = logZ - tot * (1.f / V_);
        atomicAdd(loss_out, ((1.f - EPS_) * nll + EPS_ * smooth) * (1.f / BT));
    }
}

// ---------------- driver -----------------------------------------------------
extern "C" void kernel_launch(void* const* d_in, const int* in_sizes, int n_in,
                              void* d_out, int out_size) {
    const int*   inputs  = (const int*)d_in[0];
    const int*   targets = (const int*)d_in[1];
    const float* emb     = (const float*)d_in[2];
    const float* qkv_w   = (const float*)d_in[3];
    const float* qkv_b   = (const float*)d_in[4];
    const float* aff1_w  = (const float*)d_in[5];
    const float* aff1_b  = (const float*)d_in[6];
    const float* aff2_w  = (const float*)d_in[7];
    const float* aff2_b  = (const float*)d_in[8];
    const float* ffn1_w  = (const float*)d_in[9];
    const float* ffn1_b  = (const float*)d_in[10];
    const float* ffn2_w  = (const float*)d_in[11];
    const float* ffn2_b  = (const float*)d_in[12];
    const float* ln1_s   = (const float*)d_in[13];
    const float* ln1_b   = (const float*)d_in[14];
    const float* ln2_s   = (const float*)d_in[15];
    const float* ln2_b   = (const float*)d_in[16];
    const float* head_w  = (const float*)d_in[17];
    const float* head_b  = (const float*)d_in[18];
    float* out = (float*)d_out;

    cudaFuncSetAttribute(gemm_mma<0, 0>, cudaFuncAttributeMaxDynamicSharedMemorySize, SMEM_MMA);
    cudaFuncSetAttribute(gemm_mma<1, 1>, cudaFuncAttributeMaxDynamicSharedMemorySize, SMEM_MMA);
    cudaFuncSetAttribute(gemm_mma<0, 2>, cudaFuncAttributeMaxDynamicSharedMemorySize, SMEM_MMA);
    cudaFuncSetAttribute(attn_mma, cudaFuncAttributeMaxDynamicSharedMemorySize, ATT_SMEM);

    float *px, *pqkv, *pb, *po1, *pvsuf;
    __nv_bfloat16 *ab1, *ab2, *pwqkv, *pw1, *pw2, *pw3, *pw4;
    __nv_bfloat16 *pqh, *pql, *pkh, *pkl, *pvh, *pvl;
    cudaGetSymbolAddress((void**)&px,   g_x);
    cudaGetSymbolAddress((void**)&pqkv, g_qkv);
    cudaGetSymbolAddress((void**)&pb,   g_b2);
    cudaGetSymbolAddress((void**)&po1,  g_o1);
    cudaGetSymbolAddress((void**)&ab1,  g_ab1);
    cudaGetSymbolAddress((void**)&ab2,  g_ab2);
    cudaGetSymbolAddress((void**)&pwqkv, g_wqkv);
    cudaGetSymbolAddress((void**)&pw1,  g_w1);
    cudaGetSymbolAddress((void**)&pw2,  g_w2);
    cudaGetSymbolAddress((void**)&pw3,  g_w3);
    cudaGetSymbolAddress((void**)&pw4,  g_w4);
    cudaGetSymbolAddress((void**)&pqh,  g_qh);
    cudaGetSymbolAddress((void**)&pql,  g_ql);
    cudaGetSymbolAddress((void**)&pkh,  g_kh);
    cudaGetSymbolAddress((void**)&pkl,  g_kl);
    cudaGetSymbolAddress((void**)&pvh,  g_vh);
    cudaGetSymbolAddress((void**)&pvl,  g_vl);
    cudaGetSymbolAddress((void**)&pvsuf, g_vsuf);

    detect_kernel<<<1, 256>>>(inputs, BT, 0);
    detect_kernel<<<1, 256>>>(targets, BT, 1);
    embed_kernel<<<BT, 128>>>(inputs, emb, ab1);

    conv_split_w<<<L_ * 1536, 128>>>(qkv_w,  pwqkv);
    conv_split_w<<<L_ * 512, 128>>>(aff1_w, pw1);
    conv_split_w<<<L_ * 512, 128>>>(aff2_w, pw2);
    conv_split_w<<<L_ * 512, 128>>>(ffn1_w, pw3);
    conv_split_w<<<L_ * 512, 128>>>(ffn2_w, pw4);

    for (int l = 0; l < L_; l++) {
        gemm_mma<0, 2><<<dim3(12, 32), 256, SMEM_MMA>>>(
            ab1, pwqkv + (size_t)l * 1536 * KB, qkv_b + (size_t)l * 1536,
            nullptr, nullptr, pqh, pql, pkh, pkl, pvh, pvl, 1536);
        vsuf_kernel<<<32, 64>>>(pvh, pvl, pvsuf);
        attn_mma<<<dim3(16, 32), 128, ATT_SMEM>>>(pqh, pql, pkh, pkl, pvh, pvl,
                                                  pvsuf, ab2);
        gemm_mma<1, 1><<<dim3(4, 32), 256, SMEM_MMA>>>(
            ab2, pw1 + (size_t)l * 512 * KB, aff1_b + (size_t)l * 512,
            nullptr, ab1, nullptr, nullptr, nullptr, nullptr, nullptr, nullptr, 512);
        gemm_mma<0, 0><<<dim3(4, 32), 256, SMEM_MMA>>>(
            ab1, pw2 + (size_t)l * 512 * KB, aff2_b + (size_t)l * 512,
            pb, nullptr, nullptr, nullptr, nullptr, nullptr, nullptr, nullptr, 512);
        add_ln_kernel<<<BT, 128>>>(pb, px, ln1_s + (size_t)l * 512,
                                   ln1_b + (size_t)l * 512, po1, ab2);
        gemm_mma<1, 1><<<dim3(4, 32), 256, SMEM_MMA>>>(
            ab2, pw3 + (size_t)l * 512 * KB, ffn1_b + (size_t)l * 512,
            nullptr, ab1, nullptr, nullptr, nullptr, nullptr, nullptr, nullptr, 512);
        gemm_mma<0, 0><<<dim3(4, 32), 256, SMEM_MMA>>>(
            ab1, pw4 + (size_t)l * 512 * KB, ffn2_b + (size_t)l * 512,
            pb, nullptr, nullptr, nullptr, nullptr, nullptr, nullptr, nullptr, 512);
        add_ln_kernel<<<BT, 128>>>(po1, pb, ln2_s + (size_t)l * 512,
                                   ln2_b + (size_t)l * 512, px, ab1);
    }

    float* logits_dst = (out_size >= BT * V_) ? out : pqkv;
    sgemm_nt<0><<<dim3(2, 64), 256>>>(px, head_w, head_b, logits_dst, V_, 512);

    float* loss_dst = nullptr;
    if (out_size > BT * V_) loss_dst = out + BT * V_;
    else if (out_size < BT * V_ && out_size >= 1) loss_dst = out;
    if (loss_dst) {
        zero_loss<<<1, 1>>>(loss_dst);
        loss_kernel<<<BT / 8, 256>>>(logits_dst, targets, loss_dst);
    }
}

// round 15
// speedup vs baseline: 1.4829x; 1.2724x over previous
#include <cuda_runtime.h>
#include <cuda_bf16.h>
#include <cstdint>

#define BT 4096
#define T_ 1024
#define E_ 512
#define H_ 8
#define L_ 8
#define V_ 128
#define EPS_ 0.1f
#define KB 1024   // [hi|lo] split width

// ---------------- scratch (device globals) ----------------------------------
__device__ float g_x[BT * E_];
__device__ float g_qkv[BT * 3 * E_];   // logits fallback scratch only
__device__ float g_b2[BT * E_];
__device__ float g_o1[BT * E_];
__device__ int   g_is64[2];

__device__ __nv_bfloat16 g_ab1[BT * KB];
__device__ __nv_bfloat16 g_ab2[BT * KB];
__device__ __nv_bfloat16 g_wqkv[L_ * 1536 * KB];
__device__ __nv_bfloat16 g_w1[L_ * 512 * KB];
__device__ __nv_bfloat16 g_w2[L_ * 512 * KB];
__device__ __nv_bfloat16 g_w3[L_ * 512 * KB];
__device__ __nv_bfloat16 g_w4[L_ * 512 * KB];

__device__ __nv_bfloat16 g_qh[32 * 1024 * 64];
__device__ __nv_bfloat16 g_ql[32 * 1024 * 64];
__device__ __nv_bfloat16 g_kh[32 * 1024 * 64];
__device__ __nv_bfloat16 g_kl[32 * 1024 * 64];
__device__ __nv_bfloat16 g_vh[32 * 1024 * 64];
__device__ __nv_bfloat16 g_vl[32 * 1024 * 64];
__device__ float g_vts[32 * 16 * 64];   // per-(bh, tile) V sums

// ---------------- PTX helpers ------------------------------------------------
#define SW128(o) ((o) ^ (((o) >> 3) & 0x70))
#define CP_ASYNC16(dst, src) \
    asm volatile("cp.async.cg.shared.global [%0], [%1], 16;" :: "r"(dst), "l"(src))
#define CP_COMMIT() asm volatile("cp.async.commit_group;" ::: "memory")
#define CP_WAIT1() asm volatile("cp.async.wait_group 1;" ::: "memory")
#define CP_WAIT0() asm volatile("cp.async.wait_group 0;" ::: "memory")

#define LDMATRIX_X4(r0, r1, r2, r3, addr)                                      \
    asm volatile("ldmatrix.sync.aligned.m8n8.x4.shared.b16 {%0,%1,%2,%3}, [%4];" \
                 : "=r"(r0), "=r"(r1), "=r"(r2), "=r"(r3) : "r"(addr))

#define LDMATRIX_X4T(r0, r1, r2, r3, addr)                                     \
    asm volatile("ldmatrix.sync.aligned.m8n8.x4.trans.shared.b16 {%0,%1,%2,%3}, [%4];" \
                 : "=r"(r0), "=r"(r1), "=r"(r2), "=r"(r3) : "r"(addr))

#define MMA16816(d, a, b0, b1)                                                 \
    asm volatile("mma.sync.aligned.m16n8k16.row.col.f32.bf16.bf16.f32 "        \
                 "{%0,%1,%2,%3}, {%4,%5,%6,%7}, {%8,%9}, {%0,%1,%2,%3};"       \
                 : "+f"((d)[0]), "+f"((d)[1]), "+f"((d)[2]), "+f"((d)[3])      \
                 : "r"((a)[0]), "r"((a)[1]), "r"((a)[2]), "r"((a)[3]),         \
                   "r"(b0), "r"(b1))

__device__ __forceinline__ uint32_t pack_hi_res(float a, float b, float& ra, float& rb) {
    __nv_bfloat16 h0 = __float2bfloat16(a), h1 = __float2bfloat16(b);
    ra = a - __bfloat162float(h0);
    rb = b - __bfloat162float(h1);
    return ((uint32_t)__bfloat16_as_ushort(h1) << 16) | (uint32_t)__bfloat16_as_ushort(h0);
}
__device__ __forceinline__ uint32_t pack2bf(float a, float b) {
    __nv_bfloat162 t = __floats2bfloat162_rn(a, b);
    return *reinterpret_cast<uint32_t*>(&t);
}
__device__ __forceinline__ void store_hl2(__nv_bfloat16* ab, size_t row, int col,
                                          float a, float b) {
    __nv_bfloat16 h0 = __float2bfloat16(a), h1 = __float2bfloat16(b);
    __nv_bfloat162 hh, ll;
    hh.x = h0; hh.y = h1;
    ll.x = __float2bfloat16(a - __bfloat162float(h0));
    ll.y = __float2bfloat16(b - __bfloat162float(h1));
    *(__nv_bfloat162*)&ab[row * KB + col] = hh;
    *(__nv_bfloat162*)&ab[row * KB + col + 512] = ll;
}
__device__ __forceinline__ void store_plane2(__nv_bfloat16* hp, __nv_bfloat16* lp,
                                             size_t dst, float a, float b) {
    __nv_bfloat16 h0 = __float2bfloat16(a), h1 = __float2bfloat16(b);
    __nv_bfloat162 hh, ll;
    hh.x = h0; hh.y = h1;
    ll.x = __float2bfloat16(a - __bfloat162float(h0));
    ll.y = __float2bfloat16(b - __bfloat162float(h1));
    *(__nv_bfloat162*)&hp[dst] = hh;
    *(__nv_bfloat162*)&lp[dst] = ll;
}

// ---------------- weight split conversion: [hi|lo], 2 rows/block -------------
__global__ __launch_bounds__(256) void conv_split_w(
    const float* __restrict__ X, __nv_bfloat16* __restrict__ O) {
    size_t r = (size_t)blockIdx.x * 2 + (threadIdx.x >> 7);
    int c = (threadIdx.x & 127) * 4;
    float4 v = *(const float4*)&X[r * 512 + c];
    float f[4] = {v.x, v.y, v.z, v.w};
    __nv_bfloat16 h[4], lo[4];
#pragma unroll
    for (int i = 0; i < 4; i++) {
        h[i] = __float2bfloat16(f[i]);
        lo[i] = __float2bfloat16(f[i] - __bfloat162float(h[i]));
    }
    __nv_bfloat16* o = O + r * KB + c;
    __nv_bfloat162 h01, h23, l01, l23;
    h01.x = h[0]; h01.y = h[1]; h23.x = h[2]; h23.y = h[3];
    l01.x = lo[0]; l01.y = lo[1]; l23.x = lo[2]; l23.y = lo[3];
    *(__nv_bfloat162*)&o[0] = h01;
    *(__nv_bfloat162*)&o[2] = h23;
    *(__nv_bfloat162*)&o[512] = l01;
    *(__nv_bfloat162*)&o[514] = l23;
}

// ---------------- per-tile V sums (parallel; replaces serial vsuf) -----------
__global__ __launch_bounds__(64) void vtile_kernel(
    const __nv_bfloat16* __restrict__ vh, const __nv_bfloat16* __restrict__ vl,
    float* __restrict__ vts) {
    int bh = blockIdx.x, jt = blockIdx.y, d = threadIdx.x;
    const __nv_bfloat16* ph = vh + ((size_t)bh * 1024 + jt * 64) * 64 + d;
    const __nv_bfloat16* pl = vl + ((size_t)bh * 1024 + jt * 64) * 64 + d;
    float s = 0.f;
#pragma unroll 8
    for (int t = 0; t < 64; t++)
        s += __bfloat162float(ph[(size_t)t * 64]) + __bfloat162float(pl[(size_t)t * 64]);
    vts[((size_t)bh * 16 + jt) * 64 + d] = s;
}

// ---------------- tensor-core flash attention --------------------------------
#define ATT_SMEM 81920
#define AQH 0
#define AQL 8192
#define AST(s) (16384 + (s) * 32768)

__device__ __forceinline__ void att_load_kv(
    uint32_t sb, int stage, size_t base,
    const __nv_bfloat16* kh, const __nv_bfloat16* kl,
    const __nv_bfloat16* vh, const __nv_bfloat16* vl, int kt, int tid) {
    uint32_t st = sb + AST(stage);
#pragma unroll
    for (int i = 0; i < 4; i++) {
        int g = i * 128 + tid, r = g >> 3, seg = g & 7;
        uint32_t off = SW128(r * 128 + seg * 16);
        size_t so = (base + (size_t)(kt * 64 + r) * 64) * 2 + seg * 16;
        CP_ASYNC16(st + off,         (const char*)kh + so);
        CP_ASYNC16(st + 8192 + off,  (const char*)kl + so);
        CP_ASYNC16(st + 16384 + off, (const char*)vh + so);
        CP_ASYNC16(st + 24576 + off, (const char*)vl + so);
    }
    CP_COMMIT();
}

__global__ __launch_bounds__(128) void attn_mma(
    const __nv_bfloat16* __restrict__ qh, const __nv_bfloat16* __restrict__ ql,
    const __nv_bfloat16* __restrict__ kh, const __nv_bfloat16* __restrict__ kl,
    const __nv_bfloat16* __restrict__ vh, const __nv_bfloat16* __restrict__ vl,
    const float* __restrict__ vts, __nv_bfloat16* __restrict__ AB) {
    extern __shared__ char sm[];
    __shared__ float vsufl[64];
    uint32_t sb = (uint32_t)__cvta_generic_to_shared(sm);
    int tid = threadIdx.x, wid = tid >> 5, lane = tid & 31;
    int qt = blockIdx.x, bh = blockIdx.y;
    int b = bh >> 3, h = bh & 7;
    size_t base = (size_t)bh * 1024 * 64;
    int q0 = qt * 64;
    int g = lane >> 2, qd = lane & 3;

#pragma unroll
    for (int i = 0; i < 4; i++) {
        int gg = i * 128 + tid, r = gg >> 3, seg = gg & 7;
        uint32_t off = SW128(r * 128 + seg * 16);
        size_t so = (base + (size_t)(q0 + r) * 64) * 2 + seg * 16;
        CP_ASYNC16(sb + AQH + off, (const char*)qh + so);
        CP_ASYNC16(sb + AQL + off, (const char*)ql + so);
    }
    CP_COMMIT();
    att_load_kv(sb, 0, base, kh, kl, vh, vl, 0, tid);

    // build V suffix sum for this q-tile in smem (overlaps with cp.async)
    if (tid < 64) {
        float s = 0.f;
        const float* ts = vts + (size_t)bh * 16 * 64 + tid;
        for (int jt = qt + 1; jt < 16; jt++) s += ts[jt * 64];
        vsufl[tid] = s;
    }

    float Oa[8][4];
#pragma unroll
    for (int j = 0; j < 8; j++)
#pragma unroll
        for (int e = 0; e < 4; e++) Oa[j][e] = 0.f;
    float mrow0 = 0.f, mrow1 = 0.f, lrow0 = 0.f, lrow1 = 0.f;

    int qA = q0 + wid * 16 + g, qB = qA + 8;
    uint32_t arow = (uint32_t)(wid * 16 + (lane & 15));
    uint32_t acb = (uint32_t)((lane >> 4) << 4);
    int bq = lane >> 3, br = lane & 7;
    uint32_t brbase = (uint32_t)(((bq >> 1) << 3) + br);
    uint32_t bcb = (uint32_t)((bq & 1) << 4);
    uint32_t vrow = (uint32_t)(((lane >> 3) & 1) * 8 + (lane & 7));
    uint32_t vcb = (uint32_t)((lane >> 4) << 4);

    for (int kt = 0; kt <= qt; kt++) {
        if (kt < qt) att_load_kv(sb, (kt + 1) & 1, base, kh, kl, vh, vl, kt + 1, tid);
        if (kt < qt) { CP_WAIT1(); } else { CP_WAIT0(); }
        __syncthreads();
        uint32_t st = sb + AST(kt & 1);

        float Sf[8][4];
#pragma unroll
        for (int j = 0; j < 8; j++)
#pragma unroll
            for (int e = 0; e < 4; e++) Sf[j][e] = 0.f;
#pragma unroll
        for (int ks = 0; ks < 12; ks++) {
            int grp = ks >> 2, kk2 = ks & 3;
            uint32_t qpl = sb + (grp == 1 ? AQL : AQH);
            uint32_t kpl = st + (grp == 2 ? 8192u : 0u);
            uint32_t af[4];
            LDMATRIX_X4(af[0], af[1], af[2], af[3],
                        qpl + SW128(arow * 128 + kk2 * 32 + acb));
#pragma unroll
            for (int np = 0; np < 4; np++) {
                uint32_t bf[4];
                uint32_t boff = SW128((np * 16 + brbase) * 128 + kk2 * 32 + bcb);
                LDMATRIX_X4(bf[0], bf[1], bf[2], bf[3], kpl + boff);
                MMA16816(Sf[2 * np], af, bf[0], bf[1]);
                MMA16816(Sf[2 * np + 1], af, bf[2], bf[3]);
            }
        }

        bool diag = (kt == qt);
        float tm0 = -1e30f, tm1 = -1e30f;
#pragma unroll
        for (int j = 0; j < 8; j++) {
            int k0 = kt * 64 + j * 8 + qd * 2;
            float s0 = Sf[j][0] * 0.125f, s1 = Sf[j][1] * 0.125f;
            float s2 = Sf[j][2] * 0.125f, s3 = Sf[j][3] * 0.125f;
            if (diag) {
                if (k0 > qA) s0 = 0.f;
                if (k0 + 1 > qA) s1 = 0.f;
                if (k0 > qB) s2 = 0.f;
                if (k0 + 1 > qB) s3 = 0.f;
            }
            Sf[j][0] = s0; Sf[j][1] = s1; Sf[j][2] = s2; Sf[j][3] = s3;
            tm0 = fmaxf(tm0, fmaxf(s0, s1));
            tm1 = fmaxf(tm1, fmaxf(s2, s3));
        }
        tm0 = fmaxf(tm0, __shfl_xor_sync(0xffffffffu, tm0, 1));
        tm0 = fmaxf(tm0, __shfl_xor_sync(0xffffffffu, tm0, 2));
        tm1 = fmaxf(tm1, __shfl_xor_sync(0xffffffffu, tm1, 1));
        tm1 = fmaxf(tm1, __shfl_xor_sync(0xffffffffu, tm1, 2));
        float mn0 = fmaxf(mrow0, tm0), mn1 = fmaxf(mrow1, tm1);
        float al0 = __expf(mrow0 - mn0), al1 = __expf(mrow1 - mn1);
        mrow0 = mn0; mrow1 = mn1;
        float ps0 = 0.f, ps1 = 0.f;
#pragma unroll
        for (int j = 0; j < 8; j++) {
            float p0 = __expf(Sf[j][0] - mn0), p1 = __expf(Sf[j][1] - mn0);
            float p2 = __expf(Sf[j][2] - mn1), p3 = __expf(Sf[j][3] - mn1);
            Sf[j][0] = p0; Sf[j][1] = p1; Sf[j][2] = p2; Sf[j][3] = p3;
            ps0 += p0 + p1; ps1 += p2 + p3;
            Oa[j][0] *= al0; Oa[j][1] *= al0; Oa[j][2] *= al1; Oa[j][3] *= al1;
        }
        ps0 += __shfl_xor_sync(0xffffffffu, ps0, 1);
        ps0 += __shfl_xor_sync(0xffffffffu, ps0, 2);
        ps1 += __shfl_xor_sync(0xffffffffu, ps1, 1);
        ps1 += __shfl_xor_sync(0xffffffffu, ps1, 2);
        lrow0 = lrow0 * al0 + ps0;
        lrow1 = lrow1 * al1 + ps1;

#pragma unroll
        for (int kk = 0; kk < 4; kk++) {
            int j0 = 2 * kk, j1 = 2 * kk + 1;
            float r0, r1;
            uint32_t ah[4], alr[4];
            ah[0] = pack_hi_res(Sf[j0][0], Sf[j0][1], r0, r1); alr[0] = pack2bf(r0, r1);
            ah[1] = pack_hi_res(Sf[j0][2], Sf[j0][3], r0, r1); alr[1] = pack2bf(r0, r1);
            ah[2] = pack_hi_res(Sf[j1][0], Sf[j1][1], r0, r1); alr[2] = pack2bf(r0, r1);
            ah[3] = pack_hi_res(Sf[j1][2], Sf[j1][3], r0, r1); alr[3] = pack2bf(r0, r1);
#pragma unroll
            for (int dg = 0; dg < 4; dg++) {
                uint32_t voff = SW128((kk * 16 + vrow) * 128 + dg * 32 + vcb);
                uint32_t vh0, vh1, vh2, vh3, vl0, vl1, vl2, vl3;
                LDMATRIX_X4T(vh0, vh1, vh2, vh3, st + 16384 + voff);
                LDMATRIX_X4T(vl0, vl1, vl2, vl3, st + 24576 + voff);
                MMA16816(Oa[2 * dg], ah, vh0, vh1);
                MMA16816(Oa[2 * dg], alr, vh0, vh1);
                MMA16816(Oa[2 * dg], ah, vl0, vl1);
                MMA16816(Oa[2 * dg + 1], ah, vh2, vh3);
                MMA16816(Oa[2 * dg + 1], alr, vh2, vh3);
                MMA16816(Oa[2 * dg + 1], ah, vl2, vl3);
            }
        }
        __syncthreads();
    }

    float wf0 = __expf(-mrow0), wf1 = __expf(-mrow1);
    float nfut = (float)(1024 - (qt + 1) * 64);
    float inv0 = 1.f / (lrow0 + wf0 * nfut);
    float inv1 = 1.f / (lrow1 + wf1 * nfut);
    size_t rowA = (size_t)b * 1024 + qA;
    size_t rowB = rowA + 8;
#pragma unroll
    for (int j = 0; j < 8; j++) {
        int d = j * 8 + qd * 2;
        float v0 = vsufl[d], v1 = vsufl[d + 1];
        int col = h * 64 + d;
        store_hl2(AB, rowA, col, (Oa[j][0] + wf0 * v0) * inv0,
                  (Oa[j][1] + wf0 * v1) * inv0);
        store_hl2(AB, rowB, col, (Oa[j][2] + wf1 * v0) * inv1,
                  (Oa[j][3] + wf1 * v1) * inv1);
    }
}

// ---------------- mma.sync GEMM, [hi|lo] operands, fused epilogues -----------
#define STAGE_BYTES 32768
#define SMEM_MMA (3 * STAGE_BYTES)
#define NCHUNK 24
#define EPIPITCH 132

__device__ __forceinline__ void mma_load_chunk(
    uint32_t sbase, int stage,
    const __nv_bfloat16* A, const __nv_bfloat16* Bw,
    int m0, int n0, int c, int tid) {
    uint32_t abase = sbase + stage * STAGE_BYTES;
    uint32_t bbase = abase + 16384;
    int aoff = ((c < 16) ? c : c - 16) * 128;
    int boff = ((c < 8) ? c : c - 8) * 128;
#pragma unroll
    for (int i = 0; i < 4; i++) {
        int g = i * 256 + tid, row = g >> 3, seg = g & 7;
        uint32_t dst = abase + SW128(row * 128 + seg * 16);
        const char* src = (const char*)A + (size_t)(m0 + row) * 2048 + aoff + seg * 16;
        CP_ASYNC16(dst, src);
    }
#pragma unroll
    for (int i = 0; i < 4; i++) {
        int g = i * 256 + tid, row = g >> 3, seg = g & 7;
        uint32_t dst = bbase + SW128(row * 128 + seg * 16);
        const char* src = (const char*)Bw + (size_t)(n0 + row) * 2048 + boff + seg * 16;
        CP_ASYNC16(dst, src);
    }
    CP_COMMIT();
}

template <int RELU, int OUT>
__global__ __launch_bounds__(256) void gemm_mma(
    const __nv_bfloat16* __restrict__ A, const __nv_bfloat16* __restrict__ Bw,
    const float* __restrict__ bias, float* __restrict__ C,
    __nv_bfloat16* __restrict__ AB,
    __nv_bfloat16* __restrict__ qh, __nv_bfloat16* __restrict__ ql,
    __nv_bfloat16* __restrict__ kh, __nv_bfloat16* __restrict__ kl,
    __nv_bfloat16* __restrict__ vh, __nv_bfloat16* __restrict__ vl,
    int N) {
    extern __shared__ char smem[];
    uint32_t sbase = (uint32_t)__cvta_generic_to_shared(smem);
    int tid = threadIdx.x, wid = tid >> 5, lane = tid & 31;
    int m0 = blockIdx.y * 128, n0 = blockIdx.x * 128;
    int warp_m = wid & 3, warp_n = wid >> 2;

    float acc[2][8][4];
#pragma unroll
    for (int mt = 0; mt < 2; mt++)
#pragma unroll
        for (int nt = 0; nt < 8; nt++)
#pragma unroll
            for (int e = 0; e < 4; e++) acc[mt][nt][e] = 0.f;

    mma_load_chunk(sbase, 0, A, Bw, m0, n0, 0, tid);
    mma_load_chunk(sbase, 1, A, Bw, m0, n0, 1, tid);

    int a_row = warp_m * 32 + (lane & 15);
    int a_col8 = (lane >> 4) << 3;
    int bq = lane >> 3, br = lane & 7;
    int b_n = warp_n * 64 + ((bq >> 1) << 3) + br;
    int b_col8 = (bq & 1) << 3;

    for (int c = 0; c < NCHUNK; c++) {
        if (c + 1 < NCHUNK) { CP_WAIT1(); } else { CP_WAIT0(); }
        __syncthreads();
        if (c + 2 < NCHUNK)
            mma_load_chunk(sbase, (c + 2) % 3, A, Bw, m0, n0, c + 2, tid);

        uint32_t abase = sbase + (c % 3) * STAGE_BYTES;
        uint32_t bbase = abase + 16384;
#pragma unroll
        for (int ks = 0; ks < 4; ks++) {
            uint32_t af[2][4];
#pragma unroll
            for (int mt = 0; mt < 2; mt++) {
                uint32_t off = (uint32_t)((a_row + mt * 16) * 128 + (ks * 16 + a_col8) * 2);
                LDMATRIX_X4(af[mt][0], af[mt][1], af[mt][2], af[mt][3],
                            abase + SW128(off));
            }
#pragma unroll
            for (int np = 0; np < 4; np++) {
                uint32_t bf[4];
                uint32_t off = (uint32_t)((b_n + np * 16) * 128 + (ks * 16 + b_col8) * 2);
                LDMATRIX_X4(bf[0], bf[1], bf[2], bf[3], bbase + SW128(off));
#pragma unroll
                for (int mt = 0; mt < 2; mt++) {
                    MMA16816(acc[mt][2 * np], af[mt], bf[0], bf[1]);
                    MMA16816(acc[mt][2 * np + 1], af[mt], bf[2], bf[3]);
                }
            }
        }
    }

    int g = lane >> 2, q = lane & 3;
    if (OUT == 0) {
#pragma unroll
        for (int mt = 0; mt < 2; mt++) {
            int row0 = m0 + warp_m * 32 + mt * 16 + g;
#pragma unroll
            for (int nt = 0; nt < 8; nt++) {
                int col = n0 + warp_n * 64 + nt * 8 + q * 2;
                float b0 = bias[col], b1 = bias[col + 1];
                float v0 = acc[mt][nt][0] + b0, v1 = acc[mt][nt][1] + b1;
                float v2 = acc[mt][nt][2] + b0, v3 = acc[mt][nt][3] + b1;
                if (RELU) {
                    v0 = fmaxf(v0, 0.f); v1 = fmaxf(v1, 0.f);
                    v2 = fmaxf(v2, 0.f); v3 = fmaxf(v3, 0.f);
                }
                *(float2*)&C[(size_t)row0 * N + col] = make_float2(v0, v1);
                *(float2*)&C[(size_t)(row0 + 8) * N + col] = make_float2(v2, v3);
            }
        }
    } else {
        float* sred = (float*)smem;
        __syncthreads();
#pragma unroll
        for (int mt = 0; mt < 2; mt++) {
            int r0 = warp_m * 32 + mt * 16 + g;
#pragma unroll
            for (int nt = 0; nt < 8; nt++) {
                int col = warp_n * 64 + nt * 8 + q * 2;
                float b0 = bias[n0 + col], b1 = bias[n0 + col + 1];
                float v0 = acc[mt][nt][0] + b0, v1 = acc[mt][nt][1] + b1;
                float v2 = acc[mt][nt][2] + b0, v3 = acc[mt][nt][3] + b1;
                if (RELU) {
                    v0 = fmaxf(v0, 0.f); v1 = fmaxf(v1, 0.f);
                    v2 = fmaxf(v2, 0.f); v3 = fmaxf(v3, 0.f);
                }
                *(float2*)&sred[r0 * EPIPITCH + col] = make_float2(v0, v1);
                *(float2*)&sred[(r0 + 8) * EPIPITCH + col] = make_float2(v2, v3);
            }
        }
        __syncthreads();
#pragma unroll
        for (int it = 0; it < 32; it++) {
            int p = it * 256 + tid;
            int row = p >> 6, cp = p & 63;
            int col = cp * 2;
            float v0 = sred[row * EPIPITCH + col];
            float v1 = sred[row * EPIPITCH + col + 1];
            int token = m0 + row;
            if (OUT == 1) {
                store_hl2(AB, (size_t)token, n0 + col, v0, v1);
            } else {
                int cg = n0 + col;
                int h = cg / 192, r = cg - h * 192;
                int typ = r >> 6, d = r & 63;
                __nv_bfloat16* hp = (typ == 0) ? qh : (typ == 1) ? kh : vh;
                __nv_bfloat16* lp = (typ == 0) ? ql : (typ == 1) ? kl : vl;
                int bb = token >> 10, t = token & 1023;
                size_t dst = ((size_t)(bb * 8 + h) * 1024 + t) * 64 + d;
                store_plane2(hp, lp, dst, v0, v1);
            }
        }
    }
}

// ---------------- int64-vs-int32 detection ----------------------------------
__global__ void detect_kernel(const int* __restrict__ p, int n, int slot) {
    __shared__ int red[256];
    int acc = 0;
    for (int j = 2 * threadIdx.x + 1; j < n; j += 512) acc |= p[j];
    red[threadIdx.x] = acc;
    __syncthreads();
    for (int s = 128; s > 0; s >>= 1) {
        if (threadIdx.x < s) red[threadIdx.x] |= red[threadIdx.x + s];
        __syncthreads();
    }
    if (threadIdx.x == 0) g_is64[slot] = (red[0] == 0) ? 1 : 0;
}

// ---------------- embedding gather (fp32 + split) ----------------------------
__global__ __launch_bounds__(128) void embed_kernel(
    const int* __restrict__ inp, const float* __restrict__ emb,
    __nv_bfloat16* __restrict__ AB) {
    int t = blockIdx.x;
    int tok = g_is64[0] ? inp[2 * t] : inp[t];
    int c = threadIdx.x * 4;
    float4 v = *(const float4*)(emb + (size_t)tok * E_ + c);
    *(float4*)(g_x + (size_t)t * E_ + c) = v;
    store_hl2(AB, (size_t)t, c, v.x, v.y);
    store_hl2(AB, (size_t)t, c + 2, v.z, v.w);
}

// ---------------- small SGEMM (head, N=128) ----------------------------------
template <int RELU>
__global__ __launch_bounds__(256) void sgemm_nt(
    const float* __restrict__ A, const float* __restrict__ B,
    const float* __restrict__ bias, float* __restrict__ C, int N, int K) {
    __shared__ float As[16][64];
    __shared__ float Bs[16][64];
    int tid = threadIdx.x;
    int tx = tid & 15, ty = tid >> 4;
    int m0 = blockIdx.y * 64, n0 = blockIdx.x * 64;
    int lr = tid >> 2;
    int lc = (tid & 3) * 4;
    const float* Ap = A + (size_t)(m0 + lr) * K + lc;
    const float* Bp = B + (size_t)(n0 + lr) * K + lc;
    float acc[4][4] = {};
    for (int k0 = 0; k0 < K; k0 += 16) {
        float4 a = *(const float4*)(Ap + k0);
        float4 b = *(const float4*)(Bp + k0);
        As[lc + 0][lr] = a.x; As[lc + 1][lr] = a.y; As[lc + 2][lr] = a.z; As[lc + 3][lr] = a.w;
        Bs[lc + 0][lr] = b.x; Bs[lc + 1][lr] = b.y; Bs[lc + 2][lr] = b.z; Bs[lc + 3][lr] = b.w;
        __syncthreads();
#pragma unroll
        for (int kk = 0; kk < 16; kk++) {
            float4 av = *(const float4*)&As[kk][ty * 4];
            float4 bv = *(const float4*)&Bs[kk][tx * 4];
            float ar[4] = {av.x, av.y, av.z, av.w};
            float br[4] = {bv.x, bv.y, bv.z, bv.w};
#pragma unroll
            for (int i = 0; i < 4; i++)
#pragma unroll
                for (int j = 0; j < 4; j++) acc[i][j] += ar[i] * br[j];
        }
        __syncthreads();
    }
    float b0 = bias[n0 + tx * 4 + 0];
    float b1 = bias[n0 + tx * 4 + 1];
    float b2 = bias[n0 + tx * 4 + 2];
    float b3 = bias[n0 + tx * 4 + 3];
#pragma unroll
    for (int i = 0; i < 4; i++) {
        float4 v;
        v.x = acc[i][0] + b0; v.y = acc[i][1] + b1;
        v.z = acc[i][2] + b2; v.w = acc[i][3] + b3;
        if (RELU) {
            v.x = fmaxf(v.x, 0.f); v.y = fmaxf(v.y, 0.f);
            v.z = fmaxf(v.z, 0.f); v.w = fmaxf(v.w, 0.f);
        }
        *(float4*)&C[(size_t)(m0 + ty * 4 + i) * N + n0 + tx * 4] = v;
    }
}

// ---------------- fused residual-add + layernorm (one-pass, +split) ----------
__global__ __launch_bounds__(128) void add_ln_kernel(
    const float* __restrict__ A, const float* __restrict__ R,
    const float* __restrict__ sc, const float* __restrict__ bi,
    float* __restrict__ out, __nv_bfloat16* __restrict__ AB) {
    __shared__ float red[4], red2[4];
    int t = blockIdx.x, tid = threadIdx.x;
    int e0 = tid * 4;
    float4 a = *(const float4*)&A[(size_t)t * E_ + e0];
    float4 r = *(const float4*)&R[(size_t)t * E_ + e0];
    float v0 = a.x + r.x, v1 = a.y + r.y, v2 = a.z + r.z, v3 = a.w + r.w;
    float sum = v0 + v1 + v2 + v3;
    float sq = v0 * v0 + v1 * v1 + v2 * v2 + v3 * v3;
#pragma unroll
    for (int o = 16; o; o >>= 1) {
        sum += __shfl_xor_sync(0xffffffffu, sum, o);
        sq += __shfl_xor_sync(0xffffffffu, sq, o);
    }
    int w = tid >> 5, lane = tid & 31;
    if (lane == 0) { red[w] = sum; red2[w] = sq; }
    __syncthreads();
    sum = red[0] + red[1] + red[2] + red[3];
    sq = red2[0] + red2[1] + red2[2] + red2[3];
    float mu = sum * (1.f / E_);
    float var = sq * (1.f / E_) - mu * mu;
    float rstd = rsqrtf(var + 1e-5f);
    float d0 = v0 - mu, d1 = v1 - mu, d2 = v2 - mu, d3 = v3 - mu;
    float4 s4 = *(const float4*)&sc[e0];
    float4 b4 = *(const float4*)&bi[e0];
    float4 o4;
    o4.x = d0 * rstd * s4.x + b4.x;
    o4.y = d1 * rstd * s4.y + b4.y;
    o4.z = d2 * rstd * s4.z + b4.z;
    o4.w = d3 * rstd * s4.w + b4.w;
    *(float4*)&out[(size_t)t * E_ + e0] = o4;
    store_hl2(AB, (size_t)t, e0, o4.x, o4.y);
    store_hl2(AB, (size_t)t, e0 + 2, o4.z, o4.w);
}

// ---------------- loss ------------------------------------------------------
__global__ void zero_loss(float* p) { *p = 0.f; }

__global__ __launch_bounds__(256) void loss_kernel(
    const float* __restrict__ logits, const int* __restrict__ tgt,
    float* __restrict__ loss_out) {
    int warp = threadIdx.x >> 5, lane = threadIdx.x & 31;
    int t = blockIdx.x * 8 + warp;
    const float* lp = logits + (size_t)t * V_;
    float x[4];
    float mx = -1e30f, tot = 0.f;
#pragma unroll
    for (int i = 0; i < 4; i++) {
        x[i] = lp[lane + 32 * i];
        mx = fmaxf(mx, x[i]);
        tot += x[i];
    }
#pragma unroll
    for (int o = 16; o; o >>= 1) mx = fmaxf(mx, __shfl_xor_sync(0xffffffffu, mx, o));
    float s = 0.f;
#pragma unroll
    for (int i = 0; i < 4; i++) s += expf(x[i] - mx);
#pragma unroll
    for (int o = 16; o; o >>= 1) {
        s += __shfl_xor_sync(0xffffffffu, s, o);
        tot += __shfl_xor_sync(0xffffffffu, tot, o);
    }
    if (lane == 0) {
        float logZ = mx + logf(s);
        int tv = g_is64[1] ? tgt[2 * t] : tgt[t];
        float nll = logZ - lp[tv];
        float smooth = logZ - tot * (1.f / V_);
        atomicAdd(loss_out, ((1.f - EPS_) * nll + EPS_ * smooth) * (1.f / BT));
    }
}

// ---------------- driver -----------------------------------------------------
extern "C" void kernel_launch(void* const* d_in, const int* in_sizes, int n_in,
                              void* d_out, int out_size) {
    const int*   inputs  = (const int*)d_in[0];
    const int*   targets = (const int*)d_in[1];
    const float* emb     = (const float*)d_in[2];
    const float* qkv_w   = (const float*)d_in[3];
    const float* qkv_b   = (const float*)d_in[4];
    const float* aff1_w  = (const float*)d_in[5];
    const float* aff1_b  = (const float*)d_in[6];
    const float* aff2_w  = (const float*)d_in[7];
    const float* aff2_b  = (const float*)d_in[8];
    const float* ffn1_w  = (const float*)d_in[9];
    const float* ffn1_b  = (const float*)d_in[10];
    const float* ffn2_w  = (const float*)d_in[11];
    const float* ffn2_b  = (const float*)d_in[12];
    const float* ln1_s   = (const float*)d_in[13];
    const float* ln1_b   = (const float*)d_in[14];
    const float* ln2_s   = (const float*)d_in[15];
    const float* ln2_b   = (const float*)d_in[16];
    const float* head_w  = (const float*)d_in[17];
    const float* head_b  = (const float*)d_in[18];
    float* out = (float*)d_out;

    cudaFuncSetAttribute(gemm_mma<0, 0>, cudaFuncAttributeMaxDynamicSharedMemorySize, SMEM_MMA);
    cudaFuncSetAttribute(gemm_mma<1, 1>, cudaFuncAttributeMaxDynamicSharedMemorySize, SMEM_MMA);
    cudaFuncSetAttribute(gemm_mma<0, 2>, cudaFuncAttributeMaxDynamicSharedMemorySize, SMEM_MMA);
    cudaFuncSetAttribute(attn_mma, cudaFuncAttributeMaxDynamicSharedMemorySize, ATT_SMEM);

    float *px, *pqkv, *pb, *po1, *pvts;
    __nv_bfloat16 *ab1, *ab2, *pwqkv, *pw1, *pw2, *pw3, *pw4;
    __nv_bfloat16 *pqh, *pql, *pkh, *pkl, *pvh, *pvl;
    cudaGetSymbolAddress((void**)&px,   g_x);
    cudaGetSymbolAddress((void**)&pqkv, g_qkv);
    cudaGetSymbolAddress((void**)&pb,   g_b2);
    cudaGetSymbolAddress((void**)&po1,  g_o1);
    cudaGetSymbolAddress((void**)&ab1,  g_ab1);
    cudaGetSymbolAddress((void**)&ab2,  g_ab2);
    cudaGetSymbolAddress((void**)&pwqkv, g_wqkv);
    cudaGetSymbolAddress((void**)&pw1,  g_w1);
    cudaGetSymbolAddress((void**)&pw2,  g_w2);
    cudaGetSymbolAddress((void**)&pw3,  g_w3);
    cudaGetSymbolAddress((void**)&pw4,  g_w4);
    cudaGetSymbolAddress((void**)&pqh,  g_qh);
    cudaGetSymbolAddress((void**)&pql,  g_ql);
    cudaGetSymbolAddress((void**)&pkh,  g_kh);
    cudaGetSymbolAddress((void**)&pkl,  g_kl);
    cudaGetSymbolAddress((void**)&pvh,  g_vh);
    cudaGetSymbolAddress((void**)&pvl,  g_vl);
    cudaGetSymbolAddress((void**)&pvts, g_vts);

    detect_kernel<<<1, 256>>>(inputs, BT, 0);
    detect_kernel<<<1, 256>>>(targets, BT, 1);
    embed_kernel<<<BT, 128>>>(inputs, emb, ab1);

    conv_split_w<<<L_ * 768, 256>>>(qkv_w,  pwqkv);
    conv_split_w<<<L_ * 256, 256>>>(aff1_w, pw1);
    conv_split_w<<<L_ * 256, 256>>>(aff2_w, pw2);
    conv_split_w<<<L_ * 256, 256>>>(ffn1_w, pw3);
    conv_split_w<<<L_ * 256, 256>>>(ffn2_w, pw4);

    for (int l = 0; l < L_; l++) {
        gemm_mma<0, 2><<<dim3(12, 32), 256, SMEM_MMA>>>(
            ab1, pwqkv + (size_t)l * 1536 * KB, qkv_b + (size_t)l * 1536,
            nullptr, nullptr, pqh, pql, pkh, pkl, pvh, pvl, 1536);
        vtile_kernel<<<dim3(32, 16), 64>>>(pvh, pvl, pvts);
        attn_mma<<<dim3(16, 32), 128, ATT_SMEM>>>(pqh, pql, pkh, pkl, pvh, pvl,
                                                  pvts, ab2);
        gemm_mma<1, 1><<<dim3(4, 32), 256, SMEM_MMA>>>(
            ab2, pw1 + (size_t)l * 512 * KB, aff1_b + (size_t)l * 512,
            nullptr, ab1, nullptr, nullptr, nullptr, nullptr, nullptr, nullptr, 512);
        gemm_mma<0, 0><<<dim3(4, 32), 256, SMEM_MMA>>>(
            ab1, pw2 + (size_t)l * 512 * KB, aff2_b + (size_t)l * 512,
            pb, nullptr, nullptr, nullptr, nullptr, nullptr, nullptr, nullptr, 512);
        add_ln_kernel<<<BT, 128>>>(pb, px, ln1_s + (size_t)l * 512,
                                   ln1_b + (size_t)l * 512, po1, ab2);
        gemm_mma<1, 1><<<dim3(4, 32), 256, SMEM_MMA>>>(
            ab2, pw3 + (size_t)l * 512 * KB, ffn1_b + (size_t)l * 512,
            nullptr, ab1, nullptr, nullptr, nullptr, nullptr, nullptr, nullptr, 512);
        gemm_mma<0, 0><<<dim3(4, 32), 256, SMEM_MMA>>>(
            ab1, pw4 + (size_t)l * 512 * KB, ffn2_b + (size_t)l * 512,
            pb, nullptr, nullptr, nullptr, nullptr, nullptr, nullptr, nullptr, 512);
        add_ln_kernel<<<BT, 128>>>(po1, pb, ln2_s + (size_t)l * 512,
                                   ln2_b + (size_t)l * 512, px, ab1);
    }

    float* logits_dst = (out_size >= BT * V_) ? out : pqkv;
    sgemm_nt<0><<<dim3(2, 64), 256>>>(px, head_w, head_b, logits_dst, V_, 512);

    float* loss_dst = nullptr;
    if (out_size > BT * V_) loss_dst = out + BT * V_;
    else if (out_size < BT * V_ && out_size >= 1) loss_dst = out;
    if (loss_dst) {
        zero_loss<<<1, 1>>>(loss_dst);
        loss_kernel<<<BT / 8, 256>>>(logits_dst, targets, loss_dst);
    }
}